// round 1
// baseline (speedup 1.0000x reference)
#include <cuda_runtime.h>
#include <math.h>

#define N_NODES 12000
#define F 35
#define FP 36
#define FP4 9
#define E_EDGES 192000
#define B_GRAPHS 64
#define H1 1500
#define H2 128

// ---------------- scratch (no allocation allowed) ----------------
__device__ float4 d_Q4[N_NODES * FP4];   // "keys"   = Q projection (padded to 36)
__device__ float4 d_V4[N_NODES * FP4];   // values
__device__ float4 d_Kn4[N_NODES * FP4];  // "queries" = K_new, pre-scaled by log2e/sqrt(F)
__device__ float4 d_h4[N_NODES * FP4];   // post-attention relu'd h
__device__ float d_agg[N_NODES * FP];
__device__ float d_deg[N_NODES];
__device__ float d_h2[N_NODES * FP];
__device__ float d_Weff[F * F];
__device__ float d_beff[F];
__device__ float d_Wc[F * F];
__device__ float d_bc[F];
__device__ float d_g[B_GRAPHS * FP];
__device__ float d_g1[B_GRAPHS * H1];
__device__ float d_g2[B_GRAPHS * H2];
__device__ int d_is64;

// ---------------- dtype sniffer for edge_index/batch ----------------
// If the tensors are int64 (little-endian, values < 2^31), every odd 32-bit
// word is zero. edge_index is random in [0,12000) so 16 consecutive odd words
// all being zero identifies int64 with overwhelming probability.
__global__ void detect_kernel(const int* ei) {
    if (threadIdx.x == 0 && blockIdx.x == 0) {
        int all0 = 1;
        for (int i = 0; i < 16; i++)
            if (ei[2 * i + 1] != 0) all0 = 0;
        d_is64 = all0;
    }
}

// ---------------- fold conv1d-center + concat + linear into Weff ----------------
__global__ void pre1_kernel(const float* __restrict__ Wl, const float* __restrict__ W3,
                            const float* __restrict__ W5, const float* __restrict__ b3,
                            const float* __restrict__ b5, const float* __restrict__ bl) {
    int o = blockIdx.x, k = threadIdx.x;
    if (k < F) {
        float w = Wl[o * 105 + 70 + k];
        for (int m = 0; m < F; m++) {
            w = fmaf(Wl[o * 105 + m],      W3[(m * F + k) * 3 + 1], w);
            w = fmaf(Wl[o * 105 + 35 + m], W5[(m * F + k) * 5 + 2], w);
        }
        d_Weff[o * F + k] = w;
    } else if (k == F) {
        float be = bl[o];
        for (int m = 0; m < F; m++) {
            be = fmaf(Wl[o * 105 + m],      b3[m], be);
            be = fmaf(Wl[o * 105 + 35 + m], b5[m], be);
        }
        d_beff[o] = be;
    }
}

// Wc = (Weff @ Wk) * (log2e/sqrt(F));  bc = (Weff @ bk + beff) * same
__global__ void pre2_kernel(const float* __restrict__ Wk, const float* __restrict__ bk) {
    int o = blockIdx.x, j = threadIdx.x;
    const float CS = 1.4426950408889634f / sqrtf((float)F);
    if (j < F) {
        float w = 0.f;
        for (int k = 0; k < F; k++) w = fmaf(d_Weff[o * F + k], Wk[k * F + j], w);
        d_Wc[o * F + j] = w * CS;
    } else if (j == F) {
        float b = d_beff[o];
        for (int k = 0; k < F; k++) b = fmaf(d_Weff[o * F + k], bk[k], b);
        d_bc[o] = b * CS;
    }
}

// ---------------- fused Q / V / K_new projection ----------------
__global__ __launch_bounds__(128) void proj_kernel(const float* __restrict__ x,
                                                   const float* __restrict__ Wq,
                                                   const float* __restrict__ bq,
                                                   const float* __restrict__ Wv,
                                                   const float* __restrict__ bv) {
    __shared__ float Ws[3][F * F];
    __shared__ float bs[3][F];
    __shared__ float xs[F][33];
    int tid = threadIdx.x;
    int n0 = blockIdx.x * 32;
    for (int w = tid; w < F * F; w += 128) {
        Ws[0][w] = Wq[w];
        Ws[1][w] = Wv[w];
        Ws[2][w] = d_Wc[w];
    }
    if (tid < F) {
        bs[0][tid] = bq[tid];
        bs[1][tid] = bv[tid];
        bs[2][tid] = d_bc[tid];
    }
    for (int w = tid; w < 32 * F; w += 128) {
        int n = w / F, j = w % F;
        xs[j][n] = x[(n0 + n) * F + j];
    }
    __syncthreads();
    float* Qf = (float*)d_Q4;
    float* Vf = (float*)d_V4;
    float* Kf = (float*)d_Kn4;
    for (int w = tid; w < 32 * FP; w += 128) {
        int n = w & 31, o = w >> 5;  // o warp-uniform
        int gi = (n0 + n) * FP + o;
        if (o == F) {
            Qf[gi] = 0.f; Vf[gi] = 0.f; Kf[gi] = 0.f;
        } else {
            float aq = 0.f, av = 0.f, ak = 0.f;
#pragma unroll
            for (int j = 0; j < F; j++) {
                float xv = xs[j][n];
                aq = fmaf(xv, Ws[0][o * F + j], aq);
                av = fmaf(xv, Ws[1][o * F + j], av);
                ak = fmaf(xv, Ws[2][o * F + j], ak);
            }
            Qf[gi] = aq + bs[0][o];
            Vf[gi] = av + bs[1][o];
            Kf[gi] = ak + bs[2][o];
        }
    }
}

__global__ void zero_kernel() {
    int i = blockIdx.x * blockDim.x + threadIdx.x;
    int stride = gridDim.x * blockDim.x;
    for (int k = i; k < N_NODES * FP; k += stride) d_agg[k] = 0.f;
    for (int k = i; k < N_NODES; k += stride) d_deg[k] = 0.f;
    for (int k = i; k < B_GRAPHS * FP; k += stride) d_g[k] = 0.f;
}

// ---------------- fused softmax attention: h = relu(softmax(Kn Q^T) V + V) ----------------
// 32 queries per block; 4 warps = 4 key splits; no online max (scores bounded).
__global__ __launch_bounds__(128, 3) void attn_kernel() {
    __shared__ float4 Bs[32 * FP4];
    __shared__ float4 Vs[32 * FP4];
    __shared__ float4 mO[4 * 32 * FP4];
    __shared__ float mL[4][32];
    int tid = threadIdx.x;
    int lane = tid & 31, s = tid >> 5;
    int n0 = blockIdx.x * 32;
    int qi = n0 + lane;

    float4 qv[FP4];
#pragma unroll
    for (int i = 0; i < FP4; i++) qv[i] = d_Kn4[qi * FP4 + i];
    float4 o4[FP4];
#pragma unroll
    for (int i = 0; i < FP4; i++) o4[i] = make_float4(0.f, 0.f, 0.f, 0.f);
    float l = 0.f;

    for (int t = 0; t < N_NODES / 32; t++) {
        int k0 = t * 32;
        for (int i = tid; i < 2 * 32 * FP4; i += 128) {
            if (i < 32 * FP4) Bs[i] = d_Q4[k0 * FP4 + i];
            else              Vs[i - 32 * FP4] = d_V4[k0 * FP4 + i - 32 * FP4];
        }
        __syncthreads();
#pragma unroll 2
        for (int jj = 0; jj < 8; jj++) {
            const float4* bp = Bs + (s * 8 + jj) * FP4;
            float ax = 0.f, ay = 0.f, az = 0.f, aw = 0.f;
#pragma unroll
            for (int i = 0; i < FP4; i++) {
                float4 b = bp[i];
                ax = fmaf(qv[i].x, b.x, ax);
                ay = fmaf(qv[i].y, b.y, ay);
                az = fmaf(qv[i].z, b.z, az);
                aw = fmaf(qv[i].w, b.w, aw);
            }
            float sc = (ax + ay) + (az + aw);  // already in log2 domain
            float p;
            asm("ex2.approx.f32 %0, %1;" : "=f"(p) : "f"(sc));
            l += p;
            const float4* vp = Vs + (s * 8 + jj) * FP4;
#pragma unroll
            for (int i = 0; i < FP4; i++) {
                float4 v = vp[i];
                o4[i].x = fmaf(p, v.x, o4[i].x);
                o4[i].y = fmaf(p, v.y, o4[i].y);
                o4[i].z = fmaf(p, v.z, o4[i].z);
                o4[i].w = fmaf(p, v.w, o4[i].w);
            }
        }
        __syncthreads();
    }
    // merge the 4 key-splits
    mL[s][lane] = l;
#pragma unroll
    for (int i = 0; i < FP4; i++) mO[(s * 32 + lane) * FP4 + i] = o4[i];
    __syncthreads();
    for (int w = tid; w < 32 * FP4; w += 128) {
        int q = w / FP4, i = w % FP4;
        float L = mL[0][q] + mL[1][q] + mL[2][q] + mL[3][q];
        float inv = 1.0f / L;
        float4 O = mO[(0 * 32 + q) * FP4 + i];
        float4 t1 = mO[(1 * 32 + q) * FP4 + i];
        float4 t2 = mO[(2 * 32 + q) * FP4 + i];
        float4 t3 = mO[(3 * 32 + q) * FP4 + i];
        O.x += t1.x + t2.x + t3.x;
        O.y += t1.y + t2.y + t3.y;
        O.z += t1.z + t2.z + t3.z;
        O.w += t1.w + t2.w + t3.w;
        float4 v = d_V4[(n0 + q) * FP4 + i];
        float4 r;
        r.x = fmaxf(fmaf(O.x, inv, v.x), 0.f);
        r.y = fmaxf(fmaf(O.y, inv, v.y), 0.f);
        r.z = fmaxf(fmaf(O.z, inv, v.z), 0.f);
        r.w = fmaxf(fmaf(O.w, inv, v.w), 0.f);
        d_h4[(n0 + q) * FP4 + i] = r;
    }
}

// ---------------- SAGE mean aggregation: scatter + combine ----------------
__global__ void scatter_kernel(const int* __restrict__ ei) {
    int warpId = (blockIdx.x * blockDim.x + threadIdx.x) >> 5;
    int lane = threadIdx.x & 31;
    if (warpId >= E_EDGES) return;
    int is64 = d_is64;
    int src = is64 ? ei[2 * warpId] : ei[warpId];
    int dst = is64 ? ei[2 * (E_EDGES + warpId)] : ei[E_EDGES + warpId];
    const float* hf = (const float*)d_h4;
    atomicAdd(&d_agg[dst * FP + lane], hf[src * FP + lane]);
    if (lane < 3)
        atomicAdd(&d_agg[dst * FP + 32 + lane], hf[src * FP + 32 + lane]);
    if (lane == 0) atomicAdd(&d_deg[dst], 1.0f);
}

__global__ __launch_bounds__(128) void sage_kernel(const float* __restrict__ Wll,
                                                   const float* __restrict__ bll,
                                                   const float* __restrict__ Wlr) {
    __shared__ float Wl_s[F * F], Wr_s[F * F], bl_s[F];
    __shared__ float hs[F][33], as[F][33];
    __shared__ float rd[32];
    int tid = threadIdx.x;
    int n0 = blockIdx.x * 32;
    for (int w = tid; w < F * F; w += 128) {
        Wl_s[w] = Wll[w];
        Wr_s[w] = Wlr[w];
    }
    if (tid < F) bl_s[tid] = bll[tid];
    if (tid < 32) rd[tid] = 1.0f / fmaxf(d_deg[n0 + tid], 1.0f);
    const float* hf = (const float*)d_h4;
    for (int w = tid; w < 32 * F; w += 128) {
        int n = w / F, j = w % F;
        hs[j][n] = hf[(n0 + n) * FP + j];
        as[j][n] = d_agg[(n0 + n) * FP + j];
    }
    __syncthreads();
    for (int w = tid; w < 32 * F; w += 128) {
        int n = w & 31, o = w >> 5;
        float a1 = 0.f, a2 = 0.f;
#pragma unroll
        for (int j = 0; j < F; j++) {
            a1 = fmaf(as[j][n], Wl_s[o * F + j], a1);
            a2 = fmaf(hs[j][n], Wr_s[o * F + j], a2);
        }
        float r = fmaf(a1, rd[n], bl_s[o]) + a2;
        d_h2[(n0 + n) * FP + o] = fmaxf(r, 0.f);
    }
}

// ---------------- global max pool ----------------
__global__ void pool_kernel(const int* __restrict__ batch) {
    int warpId = (blockIdx.x * blockDim.x + threadIdx.x) >> 5;
    int lane = threadIdx.x & 31;
    if (warpId >= N_NODES) return;
    int is64 = d_is64;
    int b = is64 ? batch[2 * warpId] : batch[warpId];
    int* g = (int*)d_g;
    // h2 >= 0 (relu), so int-compare of float bits is order-preserving; g init 0.
    atomicMax(&g[b * FP + lane], __float_as_int(d_h2[warpId * FP + lane]));
    if (lane < 3)
        atomicMax(&g[b * FP + 32 + lane], __float_as_int(d_h2[warpId * FP + 32 + lane]));
}

// ---------------- MLP head ----------------
__global__ __launch_bounds__(128) void mlp1_kernel(const float* __restrict__ Wg1,
                                                   const float* __restrict__ bg1) {
    __shared__ float gs[F][64];
    int tid = threadIdx.x;
    for (int w = tid; w < 64 * F; w += 128) {
        int b = w / F, d = w % F;
        gs[d][b] = d_g[b * FP + d];
    }
    __syncthreads();
    int j = blockIdx.x * 2 + (tid >> 6);
    int b = tid & 63;
    float acc = 0.f;
#pragma unroll
    for (int d = 0; d < F; d++) acc = fmaf(gs[d][b], __ldg(&Wg1[j * F + d]), acc);
    d_g1[b * H1 + j] = fmaxf(acc + bg1[j], 0.f);
}

__global__ void mlp2_kernel(const float* __restrict__ Wg2, const float* __restrict__ bg2) {
    int wid = (blockIdx.x * blockDim.x + threadIdx.x) >> 5;
    int lane = threadIdx.x & 31;
    if (wid >= B_GRAPHS * H2) return;
    int b = wid >> 7, j = wid & 127;
    float acc = 0.f;
    for (int d = lane; d < H1; d += 32)
        acc = fmaf(d_g1[b * H1 + d], Wg2[j * H1 + d], acc);
#pragma unroll
    for (int off = 16; off; off >>= 1) acc += __shfl_xor_sync(0xffffffffu, acc, off);
    if (lane == 0) d_g2[b * H2 + j] = acc + bg2[j];
}

__global__ void out_kernel(const float* __restrict__ Wo, const float* __restrict__ bo,
                           float* __restrict__ out) {
    int b = threadIdx.x;
    if (b < B_GRAPHS) {
        float acc = 0.f;
#pragma unroll
        for (int d = 0; d < H2; d++) acc = fmaf(d_g2[b * H2 + d], Wo[d], acc);
        out[b] = acc + bo[0];
    }
}

extern "C" void kernel_launch(void* const* d_in, const int* in_sizes, int n_in,
                              void* d_out, int out_size) {
    const float* x   = (const float*)d_in[0];
    const int*   ei  = (const int*)d_in[1];
    const int*   bat = (const int*)d_in[2];
    const float* Wq  = (const float*)d_in[3];
    const float* bq  = (const float*)d_in[4];
    const float* Wk  = (const float*)d_in[5];
    const float* bk  = (const float*)d_in[6];
    const float* Wv  = (const float*)d_in[7];
    const float* bv  = (const float*)d_in[8];
    const float* W3  = (const float*)d_in[9];
    const float* b3  = (const float*)d_in[10];
    const float* W5  = (const float*)d_in[11];
    const float* b5  = (const float*)d_in[12];
    const float* Wl  = (const float*)d_in[13];
    const float* bl  = (const float*)d_in[14];
    const float* Wll = (const float*)d_in[15];
    const float* bll = (const float*)d_in[16];
    const float* Wlr = (const float*)d_in[17];
    const float* Wg1 = (const float*)d_in[18];
    const float* bg1 = (const float*)d_in[19];
    const float* Wg2 = (const float*)d_in[20];
    const float* bg2 = (const float*)d_in[21];
    const float* Wo  = (const float*)d_in[22];
    const float* bo  = (const float*)d_in[23];
    float* out = (float*)d_out;

    detect_kernel<<<1, 1>>>(ei);
    pre1_kernel<<<F, F + 1>>>(Wl, W3, W5, b3, b5, bl);
    pre2_kernel<<<F, F + 1>>>(Wk, bk);
    proj_kernel<<<N_NODES / 32, 128>>>(x, Wq, bq, Wv, bv);
    zero_kernel<<<432, 256>>>();
    attn_kernel<<<N_NODES / 32, 128>>>();
    scatter_kernel<<<E_EDGES / 4, 128>>>(ei);
    sage_kernel<<<N_NODES / 32, 128>>>(Wll, bll, Wlr);
    pool_kernel<<<N_NODES / 4, 128>>>(bat);
    mlp1_kernel<<<H1 / 2, 128>>>(Wg1, bg1);
    mlp2_kernel<<<B_GRAPHS * H2 / 4, 128>>>(Wg2, bg2);
    out_kernel<<<1, 64>>>(Wo, bo, out);
}

// round 4
// speedup vs baseline: 3.4722x; 3.4722x over previous
#include <cuda_runtime.h>
#include <math.h>
#include <stdint.h>

#define N_NODES 12000
#define F 35
#define FP 36
#define FP4 9
#define F40 40
#define NQT 94            // query tiles of 128
#define QPAD (NQT * 128)  // 12032
#define NSPLIT 3
#define KT 32
#define TILES_PER_SPLIT 125   // 3 * 125 * 32 = 12000 keys
#define E_EDGES 192000
#define B_GRAPHS 64
#define H1 1500
#define H2 128

// ---------------- scratch (no allocation allowed) ----------------
__device__ float d_Kn[QPAD * F40];      // queries (=K_new), tf32-rounded, scaled by log2e/sqrt(F)
__device__ float d_Qk[N_NODES * F40];   // keys (=Q proj), tf32-rounded
__device__ float d_Vt[N_NODES * F40];   // V, tf32-rounded (GEMM operand)
__device__ float d_Vex[N_NODES * F40];  // V exact (residual)
__device__ float d_Opart[NSPLIT][QPAD * F40];
__device__ float d_lpart[NSPLIT][QPAD];
__device__ float4 d_h4[N_NODES * FP4];  // post-attention relu'd h (36-stride)
__device__ float d_agg[N_NODES * FP];
__device__ float d_deg[N_NODES];
__device__ float d_h2[N_NODES * FP];
__device__ float d_Weff[F * F];
__device__ float d_beff[F];
__device__ float d_Wc[F * F];
__device__ float d_bc[F];
__device__ float d_g[B_GRAPHS * FP];
__device__ float d_g1[B_GRAPHS * H1];
__device__ float d_g2[B_GRAPHS * H2];
__device__ int d_is64;

// cvt.rna.tf32.f32 needs a .b32 destination register; reinterpret back to float.
__device__ __forceinline__ float tf32r(float x) {
    uint32_t u;
    asm("cvt.rna.tf32.f32 %0, %1;" : "=r"(u) : "f"(x));
    return __uint_as_float(u);
}
__device__ __forceinline__ float ex2f(float x) {
    float r;
    asm("ex2.approx.f32 %0, %1;" : "=f"(r) : "f"(x));
    return r;
}
#define MMA_TF32(d0, d1, d2, d3, a0, a1, a2, a3, b0, b1)                                   \
    asm volatile(                                                                          \
        "mma.sync.aligned.m16n8k8.row.col.f32.tf32.tf32.f32 "                              \
        "{%0,%1,%2,%3},{%4,%5,%6,%7},{%8,%9},{%0,%1,%2,%3};"                               \
        : "+f"(d0), "+f"(d1), "+f"(d2), "+f"(d3)                                           \
        : "r"(a0), "r"(a1), "r"(a2), "r"(a3), "r"(b0), "r"(b1))

// ---------------- dtype sniffer for edge_index/batch ----------------
__global__ void detect_kernel(const int* ei) {
    if (threadIdx.x == 0 && blockIdx.x == 0) {
        int all0 = 1;
        for (int i = 0; i < 16; i++)
            if (ei[2 * i + 1] != 0) all0 = 0;
        d_is64 = all0;
    }
}

// ---------------- fold conv1d-center + concat + linear into Weff ----------------
__global__ void pre1_kernel(const float* __restrict__ Wl, const float* __restrict__ W3,
                            const float* __restrict__ W5, const float* __restrict__ b3,
                            const float* __restrict__ b5, const float* __restrict__ bl) {
    int o = blockIdx.x, k = threadIdx.x;
    if (k < F) {
        float w = Wl[o * 105 + 70 + k];
        for (int m = 0; m < F; m++) {
            w = fmaf(Wl[o * 105 + m],      W3[(m * F + k) * 3 + 1], w);
            w = fmaf(Wl[o * 105 + 35 + m], W5[(m * F + k) * 5 + 2], w);
        }
        d_Weff[o * F + k] = w;
    } else if (k == F) {
        float be = bl[o];
        for (int m = 0; m < F; m++) {
            be = fmaf(Wl[o * 105 + m],      b3[m], be);
            be = fmaf(Wl[o * 105 + 35 + m], b5[m], be);
        }
        d_beff[o] = be;
    }
}

// Wc = (Weff @ Wk) * (log2e/sqrt(F));  bc = (Weff @ bk + beff) * same
__global__ void pre2_kernel(const float* __restrict__ Wk, const float* __restrict__ bk) {
    int o = blockIdx.x, j = threadIdx.x;
    const float CS = 1.4426950408889634f / sqrtf((float)F);
    if (j < F) {
        float w = 0.f;
        for (int k = 0; k < F; k++) w = fmaf(d_Weff[o * F + k], Wk[k * F + j], w);
        d_Wc[o * F + j] = w * CS;
    } else if (j == F) {
        float b = d_beff[o];
        for (int k = 0; k < F; k++) b = fmaf(d_Weff[o * F + k], bk[k], b);
        d_bc[o] = b * CS;
    }
}

// ---------------- fused Q / V / K_new projection (writes 40-padded tf32 buffers) ----------------
__global__ __launch_bounds__(128) void proj_kernel(const float* __restrict__ x,
                                                   const float* __restrict__ Wq,
                                                   const float* __restrict__ bq,
                                                   const float* __restrict__ Wv,
                                                   const float* __restrict__ bv) {
    __shared__ float Ws[3][F * F];
    __shared__ float bs[3][F];
    __shared__ float xs[F][33];
    int tid = threadIdx.x;
    int n0 = blockIdx.x * 32;
    for (int w = tid; w < F * F; w += 128) {
        Ws[0][w] = Wq[w];
        Ws[1][w] = Wv[w];
        Ws[2][w] = d_Wc[w];
    }
    if (tid < F) {
        bs[0][tid] = bq[tid];
        bs[1][tid] = bv[tid];
        bs[2][tid] = d_bc[tid];
    }
    for (int w = tid; w < 32 * F; w += 128) {
        int n = w / F, j = w % F;
        int node = n0 + n;
        xs[j][n] = (node < N_NODES) ? x[node * F + j] : 0.f;
    }
    __syncthreads();
    for (int w = tid; w < 32 * F40; w += 128) {
        int n = w & 31, o = w >> 5;  // o in [0,40), warp-uniform
        int node = n0 + n;
        float q_ = 0.f, v_ = 0.f, k_ = 0.f;
        if (o < F) {
            float aq = 0.f, av = 0.f, ak = 0.f;
#pragma unroll
            for (int j = 0; j < F; j++) {
                float xv = xs[j][n];
                aq = fmaf(xv, Ws[0][o * F + j], aq);
                av = fmaf(xv, Ws[1][o * F + j], av);
                ak = fmaf(xv, Ws[2][o * F + j], ak);
            }
            q_ = aq + bs[0][o];
            v_ = av + bs[1][o];
            k_ = ak + bs[2][o];
        }
        d_Kn[node * F40 + o] = tf32r(k_);
        if (node < N_NODES) {
            d_Qk[node * F40 + o] = tf32r(q_);
            d_Vt[node * F40 + o] = tf32r(v_);
            d_Vex[node * F40 + o] = v_;
        }
    }
}

__global__ void zero_kernel() {
    int i = blockIdx.x * blockDim.x + threadIdx.x;
    int stride = gridDim.x * blockDim.x;
    for (int k = i; k < N_NODES * FP; k += stride) d_agg[k] = 0.f;
    for (int k = i; k < N_NODES; k += stride) d_deg[k] = 0.f;
    for (int k = i; k < B_GRAPHS * FP; k += stride) d_g[k] = 0.f;
}

// ---------------- tf32 flash attention (no max): partial O,l per key-split ----------------
// CTA: 256 threads = 8 warps, 128 queries (16/warp). Keys streamed in 32-key tiles.
__global__ __launch_bounds__(256, 2) void attn_kernel() {
    __shared__ __align__(16) float Ks[KT * 44];        // keys tile, stride 44 (conflict-free B loads)
    __shared__ __align__(16) float Vs[KT * F40];       // V tile, stride 40 (conflict-free B loads)
    __shared__ __align__(16) float Ps[8 * 16 * 36];    // per-warp P tiles, stride 36

    int tid = threadIdx.x;
    int w = tid >> 5, lane = tid & 31;
    int gid = lane >> 2, tig = lane & 3;
    int qbase = blockIdx.x * 128 + w * 16;
    int split = blockIdx.y;

    // stationary A fragments: this warp's 16 query rows of Kn (K=40 => 5 k-chunks)
    uint32_t A[5][4];
#pragma unroll
    for (int kc = 0; kc < 5; kc++) {
        A[kc][0] = __float_as_uint(d_Kn[(qbase + gid) * F40 + kc * 8 + tig]);
        A[kc][1] = __float_as_uint(d_Kn[(qbase + gid + 8) * F40 + kc * 8 + tig]);
        A[kc][2] = __float_as_uint(d_Kn[(qbase + gid) * F40 + kc * 8 + tig + 4]);
        A[kc][3] = __float_as_uint(d_Kn[(qbase + gid + 8) * F40 + kc * 8 + tig + 4]);
    }
    float O[5][4];
#pragma unroll
    for (int nt = 0; nt < 5; nt++)
#pragma unroll
        for (int r = 0; r < 4; r++) O[nt][r] = 0.f;
    float l0 = 0.f, l1 = 0.f;
    float* Pw = Ps + w * 16 * 36;

    const float4* gK = (const float4*)d_Qk;
    const float4* gV = (const float4*)d_Vt;
    float4* sK4 = (float4*)Ks;
    float4* sV4 = (float4*)Vs;

    int k0 = split * (TILES_PER_SPLIT * KT);
    for (int t = 0; t < TILES_PER_SPLIT; t++, k0 += KT) {
        __syncthreads();
        // stage 32 rows x 10 float4 of keys and V
        for (int i = tid; i < 320; i += 256) {
            int r = i / 10, c = i - r * 10;
            sK4[r * 11 + c] = gK[(k0 + r) * 10 + c];
            sV4[r * 10 + c] = gV[(k0 + r) * 10 + c];
        }
        __syncthreads();
        // ---- S = Kn(16x40) @ keys^T(40x32), exp2, store P ----
#pragma unroll
        for (int nt = 0; nt < 4; nt++) {
            float S0 = 0.f, S1 = 0.f, S2 = 0.f, S3 = 0.f;
#pragma unroll
            for (int kc = 0; kc < 5; kc++) {
                uint32_t b0 = __float_as_uint(Ks[(nt * 8 + gid) * 44 + kc * 8 + tig]);
                uint32_t b1 = __float_as_uint(Ks[(nt * 8 + gid) * 44 + kc * 8 + tig + 4]);
                MMA_TF32(S0, S1, S2, S3, A[kc][0], A[kc][1], A[kc][2], A[kc][3], b0, b1);
            }
            float p0 = tf32r(ex2f(S0));
            float p1 = tf32r(ex2f(S1));
            float p2 = tf32r(ex2f(S2));
            float p3 = tf32r(ex2f(S3));
            l0 += p0 + p1;
            l1 += p2 + p3;
            *(float2*)&Pw[gid * 36 + nt * 8 + 2 * tig] = make_float2(p0, p1);
            *(float2*)&Pw[(gid + 8) * 36 + nt * 8 + 2 * tig] = make_float2(p2, p3);
        }
        __syncwarp();
        // ---- O += P(16x32) @ V(32x40) ----
#pragma unroll
        for (int kc = 0; kc < 4; kc++) {
            uint32_t a0 = __float_as_uint(Pw[gid * 36 + kc * 8 + tig]);
            uint32_t a1 = __float_as_uint(Pw[(gid + 8) * 36 + kc * 8 + tig]);
            uint32_t a2 = __float_as_uint(Pw[gid * 36 + kc * 8 + tig + 4]);
            uint32_t a3 = __float_as_uint(Pw[(gid + 8) * 36 + kc * 8 + tig + 4]);
#pragma unroll
            for (int nt = 0; nt < 5; nt++) {
                uint32_t b0 = __float_as_uint(Vs[(kc * 8 + tig) * F40 + nt * 8 + gid]);
                uint32_t b1 = __float_as_uint(Vs[(kc * 8 + tig + 4) * F40 + nt * 8 + gid]);
                MMA_TF32(O[nt][0], O[nt][1], O[nt][2], O[nt][3], a0, a1, a2, a3, b0, b1);
            }
        }
    }
    // reduce l across the 4-thread group (each thread summed its own columns)
    l0 += __shfl_xor_sync(0xffffffffu, l0, 1);
    l0 += __shfl_xor_sync(0xffffffffu, l0, 2);
    l1 += __shfl_xor_sync(0xffffffffu, l1, 1);
    l1 += __shfl_xor_sync(0xffffffffu, l1, 2);

    int q0r = qbase + gid, q1r = qbase + gid + 8;
#pragma unroll
    for (int nt = 0; nt < 5; nt++) {
        *(float2*)&d_Opart[split][q0r * F40 + nt * 8 + 2 * tig] = make_float2(O[nt][0], O[nt][1]);
        *(float2*)&d_Opart[split][q1r * F40 + nt * 8 + 2 * tig] = make_float2(O[nt][2], O[nt][3]);
    }
    if (tig == 0) {
        d_lpart[split][q0r] = l0;
        d_lpart[split][q1r] = l1;
    }
}

// ---------------- merge splits: h = relu(O/l + V) ----------------
__global__ void merge_kernel() {
    int i = blockIdx.x * blockDim.x + threadIdx.x;
    if (i >= N_NODES * F) return;
    int q = i / F, f = i - q * F;
    float O = d_Opart[0][q * F40 + f] + d_Opart[1][q * F40 + f] + d_Opart[2][q * F40 + f];
    float l = d_lpart[0][q] + d_lpart[1][q] + d_lpart[2][q];
    float v = d_Vex[q * F40 + f];
    ((float*)d_h4)[q * FP + f] = fmaxf(fmaf(O, 1.0f / l, v), 0.f);
}

// ---------------- SAGE mean aggregation: scatter + combine ----------------
__global__ void scatter_kernel(const int* __restrict__ ei) {
    int warpId = (blockIdx.x * blockDim.x + threadIdx.x) >> 5;
    int lane = threadIdx.x & 31;
    if (warpId >= E_EDGES) return;
    int is64 = d_is64;
    int src = is64 ? ei[2 * warpId] : ei[warpId];
    int dst = is64 ? ei[2 * (E_EDGES + warpId)] : ei[E_EDGES + warpId];
    const float* hf = (const float*)d_h4;
    atomicAdd(&d_agg[dst * FP + lane], hf[src * FP + lane]);
    if (lane < 3)
        atomicAdd(&d_agg[dst * FP + 32 + lane], hf[src * FP + 32 + lane]);
    if (lane == 0) atomicAdd(&d_deg[dst], 1.0f);
}

__global__ __launch_bounds__(128) void sage_kernel(const float* __restrict__ Wll,
                                                   const float* __restrict__ bll,
                                                   const float* __restrict__ Wlr) {
    __shared__ float Wl_s[F * F], Wr_s[F * F], bl_s[F];
    __shared__ float hs[F][33], as[F][33];
    __shared__ float rd[32];
    int tid = threadIdx.x;
    int n0 = blockIdx.x * 32;
    for (int w = tid; w < F * F; w += 128) {
        Wl_s[w] = Wll[w];
        Wr_s[w] = Wlr[w];
    }
    if (tid < F) bl_s[tid] = bll[tid];
    if (tid < 32) rd[tid] = 1.0f / fmaxf(d_deg[n0 + tid], 1.0f);
    const float* hf = (const float*)d_h4;
    for (int w = tid; w < 32 * F; w += 128) {
        int n = w / F, j = w % F;
        hs[j][n] = hf[(n0 + n) * FP + j];
        as[j][n] = d_agg[(n0 + n) * FP + j];
    }
    __syncthreads();
    for (int w = tid; w < 32 * F; w += 128) {
        int n = w & 31, o = w >> 5;
        float a1 = 0.f, a2 = 0.f;
#pragma unroll
        for (int j = 0; j < F; j++) {
            a1 = fmaf(as[j][n], Wl_s[o * F + j], a1);
            a2 = fmaf(hs[j][n], Wr_s[o * F + j], a2);
        }
        float r = fmaf(a1, rd[n], bl_s[o]) + a2;
        d_h2[(n0 + n) * FP + o] = fmaxf(r, 0.f);
    }
}

// ---------------- global max pool ----------------
__global__ void pool_kernel(const int* __restrict__ batch) {
    int warpId = (blockIdx.x * blockDim.x + threadIdx.x) >> 5;
    int lane = threadIdx.x & 31;
    if (warpId >= N_NODES) return;
    int is64 = d_is64;
    int b = is64 ? batch[2 * warpId] : batch[warpId];
    int* g = (int*)d_g;
    atomicMax(&g[b * FP + lane], __float_as_int(d_h2[warpId * FP + lane]));
    if (lane < 3)
        atomicMax(&g[b * FP + 32 + lane], __float_as_int(d_h2[warpId * FP + 32 + lane]));
}

// ---------------- MLP head ----------------
__global__ __launch_bounds__(128) void mlp1_kernel(const float* __restrict__ Wg1,
                                                   const float* __restrict__ bg1) {
    __shared__ float gs[F][64];
    int tid = threadIdx.x;
    for (int w = tid; w < 64 * F; w += 128) {
        int b = w / F, d = w % F;
        gs[d][b] = d_g[b * FP + d];
    }
    __syncthreads();
    int j = blockIdx.x * 2 + (tid >> 6);
    int b = tid & 63;
    float acc = 0.f;
#pragma unroll
    for (int d = 0; d < F; d++) acc = fmaf(gs[d][b], __ldg(&Wg1[j * F + d]), acc);
    d_g1[b * H1 + j] = fmaxf(acc + bg1[j], 0.f);
}

__global__ void mlp2_kernel(const float* __restrict__ Wg2, const float* __restrict__ bg2) {
    int wid = (blockIdx.x * blockDim.x + threadIdx.x) >> 5;
    int lane = threadIdx.x & 31;
    if (wid >= B_GRAPHS * H2) return;
    int b = wid >> 7, j = wid & 127;
    float acc = 0.f;
    for (int d = lane; d < H1; d += 32)
        acc = fmaf(d_g1[b * H1 + d], Wg2[j * H1 + d], acc);
#pragma unroll
    for (int off = 16; off; off >>= 1) acc += __shfl_xor_sync(0xffffffffu, acc, off);
    if (lane == 0) d_g2[b * H2 + j] = acc + bg2[j];
}

__global__ void out_kernel(const float* __restrict__ Wo, const float* __restrict__ bo,
                           float* __restrict__ out) {
    int b = threadIdx.x;
    if (b < B_GRAPHS) {
        float acc = 0.f;
#pragma unroll
        for (int d = 0; d < H2; d++) acc = fmaf(d_g2[b * H2 + d], Wo[d], acc);
        out[b] = acc + bo[0];
    }
}

extern "C" void kernel_launch(void* const* d_in, const int* in_sizes, int n_in,
                              void* d_out, int out_size) {
    const float* x   = (const float*)d_in[0];
    const int*   ei  = (const int*)d_in[1];
    const int*   bat = (const int*)d_in[2];
    const float* Wq  = (const float*)d_in[3];
    const float* bq  = (const float*)d_in[4];
    const float* Wk  = (const float*)d_in[5];
    const float* bk  = (const float*)d_in[6];
    const float* Wv  = (const float*)d_in[7];
    const float* bv  = (const float*)d_in[8];
    const float* W3  = (const float*)d_in[9];
    const float* b3  = (const float*)d_in[10];
    const float* W5  = (const float*)d_in[11];
    const float* b5  = (const float*)d_in[12];
    const float* Wl  = (const float*)d_in[13];
    const float* bl  = (const float*)d_in[14];
    const float* Wll = (const float*)d_in[15];
    const float* bll = (const float*)d_in[16];
    const float* Wlr = (const float*)d_in[17];
    const float* Wg1 = (const float*)d_in[18];
    const float* bg1 = (const float*)d_in[19];
    const float* Wg2 = (const float*)d_in[20];
    const float* bg2 = (const float*)d_in[21];
    const float* Wo  = (const float*)d_in[22];
    const float* bo  = (const float*)d_in[23];
    float* out = (float*)d_out;

    detect_kernel<<<1, 1>>>(ei);
    pre1_kernel<<<F, F + 1>>>(Wl, W3, W5, b3, b5, bl);
    pre2_kernel<<<F, F + 1>>>(Wk, bk);
    proj_kernel<<<QPAD / 32, 128>>>(x, Wq, bq, Wv, bv);
    zero_kernel<<<432, 256>>>();
    attn_kernel<<<dim3(NQT, NSPLIT), 256>>>();
    merge_kernel<<<(N_NODES * F + 255) / 256, 256>>>();
    scatter_kernel<<<E_EDGES / 4, 128>>>(ei);
    sage_kernel<<<N_NODES / 32, 128>>>(Wll, bll, Wlr);
    pool_kernel<<<N_NODES / 4, 128>>>(bat);
    mlp1_kernel<<<H1 / 2, 128>>>(Wg1, bg1);
    mlp2_kernel<<<B_GRAPHS * H2 / 4, 128>>>(Wg2, bg2);
    out_kernel<<<1, 64>>>(Wo, bo, out);
}

// round 5
// speedup vs baseline: 3.4972x; 1.0072x over previous
#include <cuda_runtime.h>
#include <math.h>
#include <stdint.h>

#define N_NODES 12000
#define F 35
#define FP 36
#define FP4 9
#define F40 40
#define NQT 94            // query tiles of 128
#define QPAD (NQT * 128)  // 12032
#define NSPLIT 3
#define KT 32
#define TILES_PER_SPLIT 125   // 3 * 125 * 32 = 12000 keys
#define E_EDGES 192000
#define B_GRAPHS 64
#define H1 1500
#define H2 128

// ---------------- scratch (no allocation allowed) ----------------
__device__ float d_Kn[QPAD * F40];      // queries (=K_new), tf32-rounded, scaled by log2e/sqrt(F)
__device__ float d_Qk[N_NODES * F40];   // keys (=Q proj), tf32-rounded
__device__ float d_Vt[N_NODES * F40];   // V, tf32-rounded (GEMM operand)
__device__ float d_Vex[N_NODES * F40];  // V exact (residual)
__device__ float d_Opart[NSPLIT][QPAD * F40];
__device__ float d_lpart[NSPLIT][QPAD];
__device__ float4 d_h4[N_NODES * FP4];  // post-attention relu'd h (36-stride)
__device__ float d_agg[N_NODES * FP];
__device__ float d_deg[N_NODES];
__device__ float d_h2[N_NODES * FP];
__device__ float d_Weff[F * F];
__device__ float d_beff[F];
__device__ float d_Wc[F * F];
__device__ float d_bc[F];
__device__ float d_g[B_GRAPHS * FP];
__device__ float d_g1[B_GRAPHS * H1];
__device__ float d_g2[B_GRAPHS * H2];
__device__ int d_is64;

// cvt.rna.tf32.f32 needs a .b32 destination register; reinterpret back to float.
__device__ __forceinline__ float tf32r(float x) {
    uint32_t u;
    asm("cvt.rna.tf32.f32 %0, %1;" : "=r"(u) : "f"(x));
    return __uint_as_float(u);
}
__device__ __forceinline__ float ex2f(float x) {
    float r;
    asm("ex2.approx.f32 %0, %1;" : "=f"(r) : "f"(x));
    return r;
}
#define MMA_TF32(d0, d1, d2, d3, a0, a1, a2, a3, b0, b1)                                   \
    asm volatile(                                                                          \
        "mma.sync.aligned.m16n8k8.row.col.f32.tf32.tf32.f32 "                              \
        "{%0,%1,%2,%3},{%4,%5,%6,%7},{%8,%9},{%0,%1,%2,%3};"                               \
        : "+f"(d0), "+f"(d1), "+f"(d2), "+f"(d3)                                           \
        : "r"(a0), "r"(a1), "r"(a2), "r"(a3), "r"(b0), "r"(b1))

// ---------------- dtype sniffer for edge_index/batch ----------------
__global__ void detect_kernel(const int* ei) {
    if (threadIdx.x == 0 && blockIdx.x == 0) {
        int all0 = 1;
        for (int i = 0; i < 16; i++)
            if (ei[2 * i + 1] != 0) all0 = 0;
        d_is64 = all0;
    }
}

// ---------------- fold conv1d-center + concat + linear into Weff ----------------
__global__ void pre1_kernel(const float* __restrict__ Wl, const float* __restrict__ W3,
                            const float* __restrict__ W5, const float* __restrict__ b3,
                            const float* __restrict__ b5, const float* __restrict__ bl) {
    int o = blockIdx.x, k = threadIdx.x;
    if (k < F) {
        float w = Wl[o * 105 + 70 + k];
        for (int m = 0; m < F; m++) {
            w = fmaf(Wl[o * 105 + m],      W3[(m * F + k) * 3 + 1], w);
            w = fmaf(Wl[o * 105 + 35 + m], W5[(m * F + k) * 5 + 2], w);
        }
        d_Weff[o * F + k] = w;
    } else if (k == F) {
        float be = bl[o];
        for (int m = 0; m < F; m++) {
            be = fmaf(Wl[o * 105 + m],      b3[m], be);
            be = fmaf(Wl[o * 105 + 35 + m], b5[m], be);
        }
        d_beff[o] = be;
    }
}

// Wc = (Weff @ Wk) * (log2e/sqrt(F));  bc = (Weff @ bk + beff) * same
__global__ void pre2_kernel(const float* __restrict__ Wk, const float* __restrict__ bk) {
    int o = blockIdx.x, j = threadIdx.x;
    const float CS = 1.4426950408889634f / sqrtf((float)F);
    if (j < F) {
        float w = 0.f;
        for (int k = 0; k < F; k++) w = fmaf(d_Weff[o * F + k], Wk[k * F + j], w);
        d_Wc[o * F + j] = w * CS;
    } else if (j == F) {
        float b = d_beff[o];
        for (int k = 0; k < F; k++) b = fmaf(d_Weff[o * F + k], bk[k], b);
        d_bc[o] = b * CS;
    }
}

// ---------------- fused Q / V / K_new projection (writes 40-padded tf32 buffers) ----------------
__global__ __launch_bounds__(128) void proj_kernel(const float* __restrict__ x,
                                                   const float* __restrict__ Wq,
                                                   const float* __restrict__ bq,
                                                   const float* __restrict__ Wv,
                                                   const float* __restrict__ bv) {
    __shared__ float Ws[3][F * F];
    __shared__ float bs[3][F];
    __shared__ float xs[F][33];
    int tid = threadIdx.x;
    int n0 = blockIdx.x * 32;
    for (int w = tid; w < F * F; w += 128) {
        Ws[0][w] = Wq[w];
        Ws[1][w] = Wv[w];
        Ws[2][w] = d_Wc[w];
    }
    if (tid < F) {
        bs[0][tid] = bq[tid];
        bs[1][tid] = bv[tid];
        bs[2][tid] = d_bc[tid];
    }
    for (int w = tid; w < 32 * F; w += 128) {
        int n = w / F, j = w % F;
        int node = n0 + n;
        xs[j][n] = (node < N_NODES) ? x[node * F + j] : 0.f;
    }
    __syncthreads();
    for (int w = tid; w < 32 * F40; w += 128) {
        int n = w & 31, o = w >> 5;  // o in [0,40), warp-uniform
        int node = n0 + n;
        float q_ = 0.f, v_ = 0.f, k_ = 0.f;
        if (o < F) {
            float aq = 0.f, av = 0.f, ak = 0.f;
#pragma unroll
            for (int j = 0; j < F; j++) {
                float xv = xs[j][n];
                aq = fmaf(xv, Ws[0][o * F + j], aq);
                av = fmaf(xv, Ws[1][o * F + j], av);
                ak = fmaf(xv, Ws[2][o * F + j], ak);
            }
            q_ = aq + bs[0][o];
            v_ = av + bs[1][o];
            k_ = ak + bs[2][o];
        }
        d_Kn[node * F40 + o] = tf32r(k_);
        if (node < N_NODES) {
            d_Qk[node * F40 + o] = tf32r(q_);
            d_Vt[node * F40 + o] = tf32r(v_);
            d_Vex[node * F40 + o] = v_;
        }
    }
}

__global__ void zero_kernel() {
    int i = blockIdx.x * blockDim.x + threadIdx.x;
    int stride = gridDim.x * blockDim.x;
    for (int k = i; k < N_NODES * FP; k += stride) d_agg[k] = 0.f;
    for (int k = i; k < N_NODES; k += stride) d_deg[k] = 0.f;
    for (int k = i; k < B_GRAPHS * FP; k += stride) d_g[k] = 0.f;
}

// ---------------- tf32 flash attention (no max): partial O,l per key-split ----------------
// CTA: 256 threads = 8 warps, 128 queries (16/warp). Keys streamed in 32-key tiles.
__global__ __launch_bounds__(256, 2) void attn_kernel() {
    __shared__ __align__(16) float Ks[KT * 44];        // keys tile, stride 44 (conflict-free B loads)
    __shared__ __align__(16) float Vs[KT * F40];       // V tile, stride 40 (conflict-free B loads)
    __shared__ __align__(16) float Ps[8 * 16 * 36];    // per-warp P tiles, stride 36

    int tid = threadIdx.x;
    int w = tid >> 5, lane = tid & 31;
    int gid = lane >> 2, tig = lane & 3;
    int qbase = blockIdx.x * 128 + w * 16;
    int split = blockIdx.y;

    // stationary A fragments: this warp's 16 query rows of Kn (K=40 => 5 k-chunks)
    uint32_t A[5][4];
#pragma unroll
    for (int kc = 0; kc < 5; kc++) {
        A[kc][0] = __float_as_uint(d_Kn[(qbase + gid) * F40 + kc * 8 + tig]);
        A[kc][1] = __float_as_uint(d_Kn[(qbase + gid + 8) * F40 + kc * 8 + tig]);
        A[kc][2] = __float_as_uint(d_Kn[(qbase + gid) * F40 + kc * 8 + tig + 4]);
        A[kc][3] = __float_as_uint(d_Kn[(qbase + gid + 8) * F40 + kc * 8 + tig + 4]);
    }
    float O[5][4];
#pragma unroll
    for (int nt = 0; nt < 5; nt++)
#pragma unroll
        for (int r = 0; r < 4; r++) O[nt][r] = 0.f;
    float l0 = 0.f, l1 = 0.f;
    float* Pw = Ps + w * 16 * 36;

    const float4* gK = (const float4*)d_Qk;
    const float4* gV = (const float4*)d_Vt;
    float4* sK4 = (float4*)Ks;
    float4* sV4 = (float4*)Vs;

    int k0 = split * (TILES_PER_SPLIT * KT);
    for (int t = 0; t < TILES_PER_SPLIT; t++, k0 += KT) {
        __syncthreads();
        // stage 32 rows x 10 float4 of keys and V
        for (int i = tid; i < 320; i += 256) {
            int r = i / 10, c = i - r * 10;
            sK4[r * 11 + c] = gK[(k0 + r) * 10 + c];
            sV4[r * 10 + c] = gV[(k0 + r) * 10 + c];
        }
        __syncthreads();
        // ---- S = Kn(16x40) @ keys^T(40x32), exp2, store P ----
#pragma unroll
        for (int nt = 0; nt < 4; nt++) {
            float S0 = 0.f, S1 = 0.f, S2 = 0.f, S3 = 0.f;
#pragma unroll
            for (int kc = 0; kc < 5; kc++) {
                uint32_t b0 = __float_as_uint(Ks[(nt * 8 + gid) * 44 + kc * 8 + tig]);
                uint32_t b1 = __float_as_uint(Ks[(nt * 8 + gid) * 44 + kc * 8 + tig + 4]);
                MMA_TF32(S0, S1, S2, S3, A[kc][0], A[kc][1], A[kc][2], A[kc][3], b0, b1);
            }
            float p0 = tf32r(ex2f(S0));
            float p1 = tf32r(ex2f(S1));
            float p2 = tf32r(ex2f(S2));
            float p3 = tf32r(ex2f(S3));
            l0 += p0 + p1;
            l1 += p2 + p3;
            *(float2*)&Pw[gid * 36 + nt * 8 + 2 * tig] = make_float2(p0, p1);
            *(float2*)&Pw[(gid + 8) * 36 + nt * 8 + 2 * tig] = make_float2(p2, p3);
        }
        __syncwarp();
        // ---- O += P(16x32) @ V(32x40) ----
#pragma unroll
        for (int kc = 0; kc < 4; kc++) {
            uint32_t a0 = __float_as_uint(Pw[gid * 36 + kc * 8 + tig]);
            uint32_t a1 = __float_as_uint(Pw[(gid + 8) * 36 + kc * 8 + tig]);
            uint32_t a2 = __float_as_uint(Pw[gid * 36 + kc * 8 + tig + 4]);
            uint32_t a3 = __float_as_uint(Pw[(gid + 8) * 36 + kc * 8 + tig + 4]);
#pragma unroll
            for (int nt = 0; nt < 5; nt++) {
                uint32_t b0 = __float_as_uint(Vs[(kc * 8 + tig) * F40 + nt * 8 + gid]);
                uint32_t b1 = __float_as_uint(Vs[(kc * 8 + tig + 4) * F40 + nt * 8 + gid]);
                MMA_TF32(O[nt][0], O[nt][1], O[nt][2], O[nt][3], a0, a1, a2, a3, b0, b1);
            }
        }
    }
    // reduce l across the 4-thread group (each thread summed its own columns)
    l0 += __shfl_xor_sync(0xffffffffu, l0, 1);
    l0 += __shfl_xor_sync(0xffffffffu, l0, 2);
    l1 += __shfl_xor_sync(0xffffffffu, l1, 1);
    l1 += __shfl_xor_sync(0xffffffffu, l1, 2);

    int q0r = qbase + gid, q1r = qbase + gid + 8;
#pragma unroll
    for (int nt = 0; nt < 5; nt++) {
        *(float2*)&d_Opart[split][q0r * F40 + nt * 8 + 2 * tig] = make_float2(O[nt][0], O[nt][1]);
        *(float2*)&d_Opart[split][q1r * F40 + nt * 8 + 2 * tig] = make_float2(O[nt][2], O[nt][3]);
    }
    if (tig == 0) {
        d_lpart[split][q0r] = l0;
        d_lpart[split][q1r] = l1;
    }
}

// ---------------- merge splits: h = relu(O/l + V) ----------------
__global__ void merge_kernel() {
    int i = blockIdx.x * blockDim.x + threadIdx.x;
    if (i >= N_NODES * F) return;
    int q = i / F, f = i - q * F;
    float O = d_Opart[0][q * F40 + f] + d_Opart[1][q * F40 + f] + d_Opart[2][q * F40 + f];
    float l = d_lpart[0][q] + d_lpart[1][q] + d_lpart[2][q];
    float v = d_Vex[q * F40 + f];
    ((float*)d_h4)[q * FP + f] = fmaxf(fmaf(O, 1.0f / l, v), 0.f);
}

// ---------------- SAGE mean aggregation: scatter + combine ----------------
__global__ void scatter_kernel(const int* __restrict__ ei) {
    int warpId = (blockIdx.x * blockDim.x + threadIdx.x) >> 5;
    int lane = threadIdx.x & 31;
    if (warpId >= E_EDGES) return;
    int is64 = d_is64;
    int src = is64 ? ei[2 * warpId] : ei[warpId];
    int dst = is64 ? ei[2 * (E_EDGES + warpId)] : ei[E_EDGES + warpId];
    const float* hf = (const float*)d_h4;
    atomicAdd(&d_agg[dst * FP + lane], hf[src * FP + lane]);
    if (lane < 3)
        atomicAdd(&d_agg[dst * FP + 32 + lane], hf[src * FP + 32 + lane]);
    if (lane == 0) atomicAdd(&d_deg[dst], 1.0f);
}

__global__ __launch_bounds__(128) void sage_kernel(const float* __restrict__ Wll,
                                                   const float* __restrict__ bll,
                                                   const float* __restrict__ Wlr) {
    __shared__ float Wl_s[F * F], Wr_s[F * F], bl_s[F];
    __shared__ float hs[F][33], as[F][33];
    __shared__ float rd[32];
    int tid = threadIdx.x;
    int n0 = blockIdx.x * 32;
    for (int w = tid; w < F * F; w += 128) {
        Wl_s[w] = Wll[w];
        Wr_s[w] = Wlr[w];
    }
    if (tid < F) bl_s[tid] = bll[tid];
    if (tid < 32) rd[tid] = 1.0f / fmaxf(d_deg[n0 + tid], 1.0f);
    const float* hf = (const float*)d_h4;
    for (int w = tid; w < 32 * F; w += 128) {
        int n = w / F, j = w % F;
        hs[j][n] = hf[(n0 + n) * FP + j];
        as[j][n] = d_agg[(n0 + n) * FP + j];
    }
    __syncthreads();
    for (int w = tid; w < 32 * F; w += 128) {
        int n = w & 31, o = w >> 5;
        float a1 = 0.f, a2 = 0.f;
#pragma unroll
        for (int j = 0; j < F; j++) {
            a1 = fmaf(as[j][n], Wl_s[o * F + j], a1);
            a2 = fmaf(hs[j][n], Wr_s[o * F + j], a2);
        }
        float r = fmaf(a1, rd[n], bl_s[o]) + a2;
        d_h2[(n0 + n) * FP + o] = fmaxf(r, 0.f);
    }
}

// ---------------- global max pool ----------------
__global__ void pool_kernel(const int* __restrict__ batch) {
    int warpId = (blockIdx.x * blockDim.x + threadIdx.x) >> 5;
    int lane = threadIdx.x & 31;
    if (warpId >= N_NODES) return;
    int is64 = d_is64;
    int b = is64 ? batch[2 * warpId] : batch[warpId];
    int* g = (int*)d_g;
    atomicMax(&g[b * FP + lane], __float_as_int(d_h2[warpId * FP + lane]));
    if (lane < 3)
        atomicMax(&g[b * FP + 32 + lane], __float_as_int(d_h2[warpId * FP + 32 + lane]));
}

// ---------------- MLP head ----------------
__global__ __launch_bounds__(128) void mlp1_kernel(const float* __restrict__ Wg1,
                                                   const float* __restrict__ bg1) {
    __shared__ float gs[F][64];
    int tid = threadIdx.x;
    for (int w = tid; w < 64 * F; w += 128) {
        int b = w / F, d = w % F;
        gs[d][b] = d_g[b * FP + d];
    }
    __syncthreads();
    int j = blockIdx.x * 2 + (tid >> 6);
    int b = tid & 63;
    float acc = 0.f;
#pragma unroll
    for (int d = 0; d < F; d++) acc = fmaf(gs[d][b], __ldg(&Wg1[j * F + d]), acc);
    d_g1[b * H1 + j] = fmaxf(acc + bg1[j], 0.f);
}

__global__ void mlp2_kernel(const float* __restrict__ Wg2, const float* __restrict__ bg2) {
    int wid = (blockIdx.x * blockDim.x + threadIdx.x) >> 5;
    int lane = threadIdx.x & 31;
    if (wid >= B_GRAPHS * H2) return;
    int b = wid >> 7, j = wid & 127;
    float acc = 0.f;
    for (int d = lane; d < H1; d += 32)
        acc = fmaf(d_g1[b * H1 + d], Wg2[j * H1 + d], acc);
#pragma unroll
    for (int off = 16; off; off >>= 1) acc += __shfl_xor_sync(0xffffffffu, acc, off);
    if (lane == 0) d_g2[b * H2 + j] = acc + bg2[j];
}

__global__ void out_kernel(const float* __restrict__ Wo, const float* __restrict__ bo,
                           float* __restrict__ out) {
    int b = threadIdx.x;
    if (b < B_GRAPHS) {
        float acc = 0.f;
#pragma unroll
        for (int d = 0; d < H2; d++) acc = fmaf(d_g2[b * H2 + d], Wo[d], acc);
        out[b] = acc + bo[0];
    }
}

extern "C" void kernel_launch(void* const* d_in, const int* in_sizes, int n_in,
                              void* d_out, int out_size) {
    const float* x   = (const float*)d_in[0];
    const int*   ei  = (const int*)d_in[1];
    const int*   bat = (const int*)d_in[2];
    const float* Wq  = (const float*)d_in[3];
    const float* bq  = (const float*)d_in[4];
    const float* Wk  = (const float*)d_in[5];
    const float* bk  = (const float*)d_in[6];
    const float* Wv  = (const float*)d_in[7];
    const float* bv  = (const float*)d_in[8];
    const float* W3  = (const float*)d_in[9];
    const float* b3  = (const float*)d_in[10];
    const float* W5  = (const float*)d_in[11];
    const float* b5  = (const float*)d_in[12];
    const float* Wl  = (const float*)d_in[13];
    const float* bl  = (const float*)d_in[14];
    const float* Wll = (const float*)d_in[15];
    const float* bll = (const float*)d_in[16];
    const float* Wlr = (const float*)d_in[17];
    const float* Wg1 = (const float*)d_in[18];
    const float* bg1 = (const float*)d_in[19];
    const float* Wg2 = (const float*)d_in[20];
    const float* bg2 = (const float*)d_in[21];
    const float* Wo  = (const float*)d_in[22];
    const float* bo  = (const float*)d_in[23];
    float* out = (float*)d_out;

    detect_kernel<<<1, 1>>>(ei);
    pre1_kernel<<<F, F + 1>>>(Wl, W3, W5, b3, b5, bl);
    pre2_kernel<<<F, F + 1>>>(Wk, bk);
    proj_kernel<<<QPAD / 32, 128>>>(x, Wq, bq, Wv, bv);
    zero_kernel<<<432, 256>>>();
    attn_kernel<<<dim3(NQT, NSPLIT), 256>>>();
    merge_kernel<<<(N_NODES * F + 255) / 256, 256>>>();
    scatter_kernel<<<E_EDGES / 4, 128>>>(ei);
    sage_kernel<<<N_NODES / 32, 128>>>(Wll, bll, Wlr);
    pool_kernel<<<N_NODES / 4, 128>>>(bat);
    mlp1_kernel<<<H1 / 2, 128>>>(Wg1, bg1);
    mlp2_kernel<<<B_GRAPHS * H2 / 4, 128>>>(Wg2, bg2);
    out_kernel<<<1, 64>>>(Wo, bo, out);
}

// round 6
// speedup vs baseline: 3.8912x; 1.1126x over previous
#include <cuda_runtime.h>
#include <math.h>
#include <stdint.h>

#define N_NODES 12000
#define F 35
#define FP 36
#define F40 40
#define QT 256
#define NQT 47            // query tiles of 256
#define QPAD (NQT * QT)   // 12032
#define NSPLIT 3
#define KT 32
#define TILES_PER_SPLIT 125
#define E_EDGES 192000
#define B_GRAPHS 64
#define H1 1500
#define H2 128

// ---------------- scratch ----------------
__device__ float d_Kn[QPAD * F40];
__device__ float d_Qk[N_NODES * F40];
__device__ float d_Vt[N_NODES * F40];
__device__ float d_Vex[N_NODES * F40];
__device__ float d_Opart[NSPLIT][QPAD * F40];
__device__ float d_lpart[NSPLIT][QPAD];
__device__ float4 d_h4[N_NODES * 9];     // h, 36-stride (9 float4/row)
__device__ float4 d_agg4[N_NODES * 9];
__device__ float d_deg[N_NODES];
__device__ float d_Weff[F * F];
__device__ float d_beff[F];
__device__ float d_Wc[F * F];
__device__ float d_bc[F];
__device__ float d_g[B_GRAPHS * FP];
__device__ float d_g1[B_GRAPHS * H1];
__device__ float d_g2[B_GRAPHS * H2];
__device__ int d_is64;

__device__ __forceinline__ float tf32r(float x) {
    uint32_t u;
    asm("cvt.rna.tf32.f32 %0, %1;" : "=r"(u) : "f"(x));
    return __uint_as_float(u);
}
__device__ __forceinline__ float ex2f(float x) {
    float r;
    asm("ex2.approx.f32 %0, %1;" : "=f"(r) : "f"(x));
    return r;
}
#define MMA_TF32(d0, d1, d2, d3, a0, a1, a2, a3, b0, b1)                                   \
    asm volatile(                                                                          \
        "mma.sync.aligned.m16n8k8.row.col.f32.tf32.tf32.f32 "                              \
        "{%0,%1,%2,%3},{%4,%5,%6,%7},{%8,%9},{%0,%1,%2,%3};"                               \
        : "+f"(d0), "+f"(d1), "+f"(d2), "+f"(d3)                                           \
        : "r"(a0), "r"(a1), "r"(a2), "r"(a3), "r"(b0), "r"(b1))
#define CPA16(dst, src) \
    asm volatile("cp.async.cg.shared.global [%0], [%1], 16;" :: "r"(dst), "l"(src))
#define CPA_COMMIT() asm volatile("cp.async.commit_group;")
#define CPA_WAIT1()  asm volatile("cp.async.wait_group 1;")

__device__ __forceinline__ void red4(float4* p, float4 v) {
    asm volatile("red.global.add.v4.f32 [%0], {%1,%2,%3,%4};"
                 :: "l"(p), "f"(v.x), "f"(v.y), "f"(v.z), "f"(v.w) : "memory");
}
__device__ __forceinline__ void red1(float* p, float v) {
    asm volatile("red.global.add.f32 [%0], %1;" :: "l"(p), "f"(v) : "memory");
}

// ---------------- dtype sniffer ----------------
__global__ void detect_kernel(const int* ei) {
    if (threadIdx.x == 0 && blockIdx.x == 0) {
        int all0 = 1;
        for (int i = 0; i < 16; i++)
            if (ei[2 * i + 1] != 0) all0 = 0;
        d_is64 = all0;
    }
}

// ---------------- fold conv1d-center + concat + linear ----------------
__global__ void pre1_kernel(const float* __restrict__ Wl, const float* __restrict__ W3,
                            const float* __restrict__ W5, const float* __restrict__ b3,
                            const float* __restrict__ b5, const float* __restrict__ bl) {
    int o = blockIdx.x, k = threadIdx.x;
    if (k < F) {
        float w = Wl[o * 105 + 70 + k];
        for (int m = 0; m < F; m++) {
            w = fmaf(Wl[o * 105 + m],      W3[(m * F + k) * 3 + 1], w);
            w = fmaf(Wl[o * 105 + 35 + m], W5[(m * F + k) * 5 + 2], w);
        }
        d_Weff[o * F + k] = w;
    } else if (k == F) {
        float be = bl[o];
        for (int m = 0; m < F; m++) {
            be = fmaf(Wl[o * 105 + m],      b3[m], be);
            be = fmaf(Wl[o * 105 + 35 + m], b5[m], be);
        }
        d_beff[o] = be;
    }
}

__global__ void pre2_kernel(const float* __restrict__ Wk, const float* __restrict__ bk) {
    int o = blockIdx.x, j = threadIdx.x;
    const float CS = 1.4426950408889634f / sqrtf((float)F);
    if (j < F) {
        float w = 0.f;
        for (int k = 0; k < F; k++) w = fmaf(d_Weff[o * F + k], Wk[k * F + j], w);
        d_Wc[o * F + j] = w * CS;
    } else if (j == F) {
        float b = d_beff[o];
        for (int k = 0; k < F; k++) b = fmaf(d_Weff[o * F + k], bk[k], b);
        d_bc[o] = b * CS;
    }
}

// ---------------- Q / V / Kn projection: thread-per-node, x in registers ----------------
__global__ __launch_bounds__(128) void proj_kernel(const float* __restrict__ x,
                                                   const float* __restrict__ Wq,
                                                   const float* __restrict__ bq,
                                                   const float* __restrict__ Wv,
                                                   const float* __restrict__ bv) {
    __shared__ __align__(16) float W[105 * 36];  // rows 0-34 Wq, 35-69 Wv, 70-104 Wc
    __shared__ float bsh[112];
    int tid = threadIdx.x;
    for (int i = tid; i < 105 * 36; i += 128) {
        int r = i / 36, c = i - r * 36;
        float v = 0.f;
        if (c < 35) {
            if (r < 35)      v = Wq[r * 35 + c];
            else if (r < 70) v = Wv[(r - 35) * 35 + c];
            else             v = d_Wc[(r - 70) * 35 + c];
        }
        W[i] = v;
    }
    if (tid < 105) {
        bsh[tid] = (tid < 35) ? bq[tid] : (tid < 70) ? bv[tid - 35] : d_bc[tid - 70];
    }
    int node = blockIdx.x * 128 + tid;
    float4 xv[9];
#pragma unroll
    for (int c = 0; c < 9; c++) xv[c] = make_float4(0.f, 0.f, 0.f, 0.f);
    if (node < N_NODES) {
        float* xf = (float*)xv;
#pragma unroll
        for (int j = 0; j < 35; j++) xf[j] = x[node * 35 + j];
    }
    __syncthreads();

    float out_t[40], out_e[40];
#pragma unroll
    for (int c = 0; c < 5; c++) { out_t[35 + c] = 0.f; out_e[35 + c] = 0.f; }

    // ---- Kn (all nodes incl. pad; pad rows forced to 0) ----
#pragma unroll
    for (int o = 0; o < 35; o++) {
        const float4* wr = (const float4*)(W + (70 + o) * 36);
        float ax = 0.f, ay = 0.f, az = 0.f, aw = 0.f;
#pragma unroll
        for (int c = 0; c < 9; c++) {
            float4 wv = wr[c];
            ax = fmaf(wv.x, xv[c].x, ax);
            ay = fmaf(wv.y, xv[c].y, ay);
            az = fmaf(wv.z, xv[c].z, az);
            aw = fmaf(wv.w, xv[c].w, aw);
        }
        float acc = (ax + ay) + (az + aw) + bsh[70 + o];
        out_t[o] = (node < N_NODES) ? tf32r(acc) : 0.f;
    }
#pragma unroll
    for (int c = 0; c < 10; c++)
        ((float4*)(d_Kn + (size_t)node * F40))[c] = ((float4*)out_t)[c];

    if (node >= N_NODES) return;

    // ---- Q ----
#pragma unroll
    for (int o = 0; o < 35; o++) {
        const float4* wr = (const float4*)(W + o * 36);
        float ax = 0.f, ay = 0.f, az = 0.f, aw = 0.f;
#pragma unroll
        for (int c = 0; c < 9; c++) {
            float4 wv = wr[c];
            ax = fmaf(wv.x, xv[c].x, ax);
            ay = fmaf(wv.y, xv[c].y, ay);
            az = fmaf(wv.z, xv[c].z, az);
            aw = fmaf(wv.w, xv[c].w, aw);
        }
        out_t[o] = tf32r((ax + ay) + (az + aw) + bsh[o]);
    }
#pragma unroll
    for (int c = 0; c < 10; c++)
        ((float4*)(d_Qk + (size_t)node * F40))[c] = ((float4*)out_t)[c];

    // ---- V (tf32 + exact) ----
#pragma unroll
    for (int o = 0; o < 35; o++) {
        const float4* wr = (const float4*)(W + (35 + o) * 36);
        float ax = 0.f, ay = 0.f, az = 0.f, aw = 0.f;
#pragma unroll
        for (int c = 0; c < 9; c++) {
            float4 wv = wr[c];
            ax = fmaf(wv.x, xv[c].x, ax);
            ay = fmaf(wv.y, xv[c].y, ay);
            az = fmaf(wv.z, xv[c].z, az);
            aw = fmaf(wv.w, xv[c].w, aw);
        }
        float acc = (ax + ay) + (az + aw) + bsh[35 + o];
        out_e[o] = acc;
        out_t[o] = tf32r(acc);
    }
#pragma unroll
    for (int c = 0; c < 10; c++) {
        ((float4*)(d_Vt  + (size_t)node * F40))[c] = ((float4*)out_t)[c];
        ((float4*)(d_Vex + (size_t)node * F40))[c] = ((float4*)out_e)[c];
    }
}

__global__ void zero_kernel() {
    int i = blockIdx.x * blockDim.x + threadIdx.x;
    int stride = gridDim.x * blockDim.x;
    float* af = (float*)d_agg4;
    for (int k = i; k < N_NODES * FP; k += stride) af[k] = 0.f;
    for (int k = i; k < N_NODES; k += stride) d_deg[k] = 0.f;
    for (int k = i; k < B_GRAPHS * FP; k += stride) d_g[k] = 0.f;
}

// ---------------- tf32 flash attention, 256 q/CTA, double-buffered cp.async ----------------
// dyn smem: Ks[2][32*44] | Vs[2][32*40] | Ps[16][16*36]  = 58368 bytes
__global__ __launch_bounds__(512, 1) void attn_kernel() {
    extern __shared__ __align__(16) float sm[];
    float* Ks = sm;                  // 2 * 1408 floats
    float* Vs = sm + 2816;           // 2 * 1280 floats
    float* Ps = sm + 5376;           // 16 * 576 floats
    uint32_t smb = (uint32_t)__cvta_generic_to_shared(sm);

    int tid = threadIdx.x;
    int w = tid >> 5, lane = tid & 31;
    int gid = lane >> 2, tig = lane & 3;
    int qbase = blockIdx.x * QT + w * 16;
    int split = blockIdx.y;

    uint32_t A[5][4];
#pragma unroll
    for (int kc = 0; kc < 5; kc++) {
        A[kc][0] = __float_as_uint(d_Kn[(qbase + gid) * F40 + kc * 8 + tig]);
        A[kc][1] = __float_as_uint(d_Kn[(qbase + gid + 8) * F40 + kc * 8 + tig]);
        A[kc][2] = __float_as_uint(d_Kn[(qbase + gid) * F40 + kc * 8 + tig + 4]);
        A[kc][3] = __float_as_uint(d_Kn[(qbase + gid + 8) * F40 + kc * 8 + tig + 4]);
    }
    float O[5][4];
#pragma unroll
    for (int nt = 0; nt < 5; nt++)
#pragma unroll
        for (int r = 0; r < 4; r++) O[nt][r] = 0.f;
    float l0 = 0.f, l1 = 0.f;
    float* Pw = Ps + w * 576;

    int kstart = split * (TILES_PER_SPLIT * KT);

    // prologue: stage tile 0 into buf 0
    for (int i = tid; i < 640; i += 512) {
        if (i < 320) {
            int r = i / 10, c = i - r * 10;
            CPA16(smb + r * 176 + c * 16, d_Qk + (kstart + r) * F40 + c * 4);
        } else {
            int j = i - 320; int r = j / 10, c = j - r * 10;
            CPA16(smb + 11264 + r * 160 + c * 16, d_Vt + (kstart + r) * F40 + c * 4);
        }
    }
    CPA_COMMIT();

    for (int t = 0; t < TILES_PER_SPLIT; t++) {
        int cur = t & 1;
        if (t < TILES_PER_SPLIT - 1) {
            int nb = cur ^ 1;
            int k0 = kstart + (t + 1) * KT;
            for (int i = tid; i < 640; i += 512) {
                if (i < 320) {
                    int r = i / 10, c = i - r * 10;
                    CPA16(smb + nb * 5632 + r * 176 + c * 16, d_Qk + (k0 + r) * F40 + c * 4);
                } else {
                    int j = i - 320; int r = j / 10, c = j - r * 10;
                    CPA16(smb + 11264 + nb * 5120 + r * 160 + c * 16, d_Vt + (k0 + r) * F40 + c * 4);
                }
            }
        }
        CPA_COMMIT();
        CPA_WAIT1();
        __syncthreads();

        const float* K_ = Ks + cur * 1408;
        const float* V_ = Vs + cur * 1280;
        // ---- S = Kn(16x40) @ keys^T(40x32), exp2, store P ----
#pragma unroll
        for (int nt = 0; nt < 4; nt++) {
            float S0 = 0.f, S1 = 0.f, S2 = 0.f, S3 = 0.f;
#pragma unroll
            for (int kc = 0; kc < 5; kc++) {
                uint32_t b0 = __float_as_uint(K_[(nt * 8 + gid) * 44 + kc * 8 + tig]);
                uint32_t b1 = __float_as_uint(K_[(nt * 8 + gid) * 44 + kc * 8 + tig + 4]);
                MMA_TF32(S0, S1, S2, S3, A[kc][0], A[kc][1], A[kc][2], A[kc][3], b0, b1);
            }
            float p0 = tf32r(ex2f(S0));
            float p1 = tf32r(ex2f(S1));
            float p2 = tf32r(ex2f(S2));
            float p3 = tf32r(ex2f(S3));
            l0 += p0 + p1;
            l1 += p2 + p3;
            *(float2*)&Pw[gid * 36 + nt * 8 + 2 * tig] = make_float2(p0, p1);
            *(float2*)&Pw[(gid + 8) * 36 + nt * 8 + 2 * tig] = make_float2(p2, p3);
        }
        __syncwarp();
        // ---- O += P(16x32) @ V(32x40) ----
#pragma unroll
        for (int kc = 0; kc < 4; kc++) {
            uint32_t a0 = __float_as_uint(Pw[gid * 36 + kc * 8 + tig]);
            uint32_t a1 = __float_as_uint(Pw[(gid + 8) * 36 + kc * 8 + tig]);
            uint32_t a2 = __float_as_uint(Pw[gid * 36 + kc * 8 + tig + 4]);
            uint32_t a3 = __float_as_uint(Pw[(gid + 8) * 36 + kc * 8 + tig + 4]);
#pragma unroll
            for (int nt = 0; nt < 5; nt++) {
                uint32_t b0 = __float_as_uint(V_[(kc * 8 + tig) * F40 + nt * 8 + gid]);
                uint32_t b1 = __float_as_uint(V_[(kc * 8 + tig + 4) * F40 + nt * 8 + gid]);
                MMA_TF32(O[nt][0], O[nt][1], O[nt][2], O[nt][3], a0, a1, a2, a3, b0, b1);
            }
        }
        __syncthreads();
    }

    l0 += __shfl_xor_sync(0xffffffffu, l0, 1);
    l0 += __shfl_xor_sync(0xffffffffu, l0, 2);
    l1 += __shfl_xor_sync(0xffffffffu, l1, 1);
    l1 += __shfl_xor_sync(0xffffffffu, l1, 2);

    int q0r = qbase + gid, q1r = qbase + gid + 8;
#pragma unroll
    for (int nt = 0; nt < 5; nt++) {
        *(float2*)&d_Opart[split][q0r * F40 + nt * 8 + 2 * tig] = make_float2(O[nt][0], O[nt][1]);
        *(float2*)&d_Opart[split][q1r * F40 + nt * 8 + 2 * tig] = make_float2(O[nt][2], O[nt][3]);
    }
    if (tig == 0) {
        d_lpart[split][q0r] = l0;
        d_lpart[split][q1r] = l1;
    }
}

// ---------------- merge splits: h = relu(O/l + V) ----------------
__global__ void merge_kernel() {
    int i = blockIdx.x * blockDim.x + threadIdx.x;
    if (i >= N_NODES * F) return;
    int q = i / F, f = i - q * F;
    float O = d_Opart[0][q * F40 + f] + d_Opart[1][q * F40 + f] + d_Opart[2][q * F40 + f];
    float l = d_lpart[0][q] + d_lpart[1][q] + d_lpart[2][q];
    float v = d_Vex[q * F40 + f];
    ((float*)d_h4)[q * FP + f] = fmaxf(fmaf(O, 1.0f / l, v), 0.f);
}

// ---------------- SAGE scatter: thread-per-edge, v4 reductions ----------------
__global__ void scatter_kernel(const int* __restrict__ ei) {
    int e = blockIdx.x * blockDim.x + threadIdx.x;
    if (e >= E_EDGES) return;
    int is64 = d_is64;
    int src = is64 ? ei[2 * e] : ei[e];
    int dst = is64 ? ei[2 * (E_EDGES + e)] : ei[E_EDGES + e];
    const float4* hs = d_h4 + src * 9;
    float4* ag = d_agg4 + dst * 9;
#pragma unroll
    for (int i = 0; i < 9; i++) red4(ag + i, hs[i]);
    red1(&d_deg[dst], 1.0f);
}

// ---------------- SAGE combine + fused global max pool ----------------
__global__ __launch_bounds__(128) void sage_kernel(const float* __restrict__ Wll,
                                                   const float* __restrict__ bll,
                                                   const float* __restrict__ Wlr,
                                                   const int* __restrict__ bat) {
    __shared__ float Wl_s[F * F], Wr_s[F * F], bl_s[F];
    __shared__ float hs[F][33], as[F][33];
    __shared__ float rd[32];
    __shared__ int bs[32];
    int tid = threadIdx.x;
    int n0 = blockIdx.x * 32;
    int is64 = d_is64;
    for (int w = tid; w < F * F; w += 128) {
        Wl_s[w] = Wll[w];
        Wr_s[w] = Wlr[w];
    }
    if (tid < F) bl_s[tid] = bll[tid];
    if (tid < 32) {
        rd[tid] = 1.0f / fmaxf(d_deg[n0 + tid], 1.0f);
        int node = n0 + tid;
        bs[tid] = is64 ? bat[2 * node] : bat[node];
    }
    const float* hf = (const float*)d_h4;
    const float* af = (const float*)d_agg4;
    for (int w = tid; w < 32 * F; w += 128) {
        int n = w / F, j = w % F;
        hs[j][n] = hf[(n0 + n) * FP + j];
        as[j][n] = af[(n0 + n) * FP + j];
    }
    __syncthreads();
    for (int w = tid; w < 32 * F; w += 128) {
        int n = w & 31, o = w >> 5;
        float a1 = 0.f, a2 = 0.f;
#pragma unroll
        for (int j = 0; j < F; j++) {
            a1 = fmaf(as[j][n], Wl_s[o * F + j], a1);
            a2 = fmaf(hs[j][n], Wr_s[o * F + j], a2);
        }
        float r = fmaf(a1, rd[n], bl_s[o]) + a2;
        r = fmaxf(r, 0.f);
        // h2 >= 0; int-compare of non-negative float bits is order-preserving; g zeroed.
        atomicMax((int*)&d_g[bs[n] * FP + o], __float_as_int(r));
    }
}

// ---------------- MLP head ----------------
__global__ __launch_bounds__(128) void mlp1_kernel(const float* __restrict__ Wg1,
                                                   const float* __restrict__ bg1) {
    __shared__ float gs[F][64];
    int tid = threadIdx.x;
    for (int w = tid; w < 64 * F; w += 128) {
        int b = w / F, d = w % F;
        gs[d][b] = d_g[b * FP + d];
    }
    __syncthreads();
    int j = blockIdx.x * 2 + (tid >> 6);
    int b = tid & 63;
    float acc = 0.f;
#pragma unroll
    for (int d = 0; d < F; d++) acc = fmaf(gs[d][b], __ldg(&Wg1[j * F + d]), acc);
    d_g1[b * H1 + j] = fmaxf(acc + bg1[j], 0.f);
}

__global__ void mlp2_kernel(const float* __restrict__ Wg2, const float* __restrict__ bg2) {
    int wid = (blockIdx.x * blockDim.x + threadIdx.x) >> 5;
    int lane = threadIdx.x & 31;
    if (wid >= B_GRAPHS * H2) return;
    int b = wid >> 7, j = wid & 127;
    float acc = 0.f;
    for (int d = lane; d < H1; d += 32)
        acc = fmaf(d_g1[b * H1 + d], Wg2[j * H1 + d], acc);
#pragma unroll
    for (int off = 16; off; off >>= 1) acc += __shfl_xor_sync(0xffffffffu, acc, off);
    if (lane == 0) d_g2[b * H2 + j] = acc + bg2[j];
}

__global__ void out_kernel(const float* __restrict__ Wo, const float* __restrict__ bo,
                           float* __restrict__ out) {
    int b = threadIdx.x;
    if (b < B_GRAPHS) {
        float acc = 0.f;
#pragma unroll
        for (int d = 0; d < H2; d++) acc = fmaf(d_g2[b * H2 + d], Wo[d], acc);
        out[b] = acc + bo[0];
    }
}

extern "C" void kernel_launch(void* const* d_in, const int* in_sizes, int n_in,
                              void* d_out, int out_size) {
    const float* x   = (const float*)d_in[0];
    const int*   ei  = (const int*)d_in[1];
    const int*   bat = (const int*)d_in[2];
    const float* Wq  = (const float*)d_in[3];
    const float* bq  = (const float*)d_in[4];
    const float* Wk  = (const float*)d_in[5];
    const float* bk  = (const float*)d_in[6];
    const float* Wv  = (const float*)d_in[7];
    const float* bv  = (const float*)d_in[8];
    const float* W3  = (const float*)d_in[9];
    const float* b3  = (const float*)d_in[10];
    const float* W5  = (const float*)d_in[11];
    const float* b5  = (const float*)d_in[12];
    const float* Wl  = (const float*)d_in[13];
    const float* bl  = (const float*)d_in[14];
    const float* Wll = (const float*)d_in[15];
    const float* bll = (const float*)d_in[16];
    const float* Wlr = (const float*)d_in[17];
    const float* Wg1 = (const float*)d_in[18];
    const float* bg1 = (const float*)d_in[19];
    const float* Wg2 = (const float*)d_in[20];
    const float* bg2 = (const float*)d_in[21];
    const float* Wo  = (const float*)d_in[22];
    const float* bo  = (const float*)d_in[23];
    float* out = (float*)d_out;

    const int ATTN_SMEM = 58368;
    cudaFuncSetAttribute(attn_kernel, cudaFuncAttributeMaxDynamicSharedMemorySize, ATTN_SMEM);

    detect_kernel<<<1, 1>>>(ei);
    pre1_kernel<<<F, F + 1>>>(Wl, W3, W5, b3, b5, bl);
    pre2_kernel<<<F, F + 1>>>(Wk, bk);
    proj_kernel<<<QPAD / 128, 128>>>(x, Wq, bq, Wv, bv);
    zero_kernel<<<432, 256>>>();
    attn_kernel<<<dim3(NQT, NSPLIT), 512, ATTN_SMEM>>>();
    merge_kernel<<<(N_NODES * F + 255) / 256, 256>>>();
    scatter_kernel<<<(E_EDGES + 255) / 256, 256>>>(ei);
    sage_kernel<<<N_NODES / 32, 128>>>(Wll, bll, Wlr, bat);
    mlp1_kernel<<<H1 / 2, 128>>>(Wg1, bg1);
    mlp2_kernel<<<B_GRAPHS * H2 / 4, 128>>>(Wg2, bg2);
    out_kernel<<<1, 64>>>(Wo, bo, out);
}

// round 7
// speedup vs baseline: 5.6787x; 1.4594x over previous
#include <cuda_runtime.h>
#include <cuda_bf16.h>
#include <math.h>
#include <stdint.h>

#define N_NODES 12000
#define F 35
#define FP 36
#define QPAD 12032
#define NSPLIT 3
#define KT 32
#define TILES_PER_SPLIT 125
#define E_EDGES 192000
#define B_GRAPHS 64
#define H1 1500
#define H2 128

// ---------------- scratch ----------------
// Kn/Qk: [12032][48] bf16 (24 words/row). VtT: [40][12032] bf16 transposed.
__device__ __align__(16) uint32_t d_Kn32[QPAD * 24];
__device__ __align__(16) uint32_t d_Qk32[QPAD * 24];
__device__ __align__(16) uint16_t d_VtT[40 * QPAD];
__device__ float d_Vex[QPAD * 40];
__device__ float d_Opart[NSPLIT][QPAD * 40];
__device__ float4 d_h4[N_NODES * 9];    // h, 36-stride
__device__ float4 d_agg4[N_NODES * 9];
__device__ float d_deg[N_NODES];
__device__ float d_Weff[F * F];
__device__ float d_beff[F];
__device__ float d_Wc[F * F];
__device__ float d_bc[F];
__device__ float d_g[B_GRAPHS * FP];
__device__ float d_g1[B_GRAPHS * H1];
__device__ float d_g2[B_GRAPHS * H2];
__device__ int d_is64;

__device__ __forceinline__ float ex2f(float x) {
    float r;
    asm("ex2.approx.f32 %0, %1;" : "=f"(r) : "f"(x));
    return r;
}
// pack {lo, hi} floats into bf16x2 (hi goes to upper half)
__device__ __forceinline__ uint32_t packbf(float hi, float lo) {
    uint32_t r;
    asm("cvt.rn.bf16x2.f32 %0, %1, %2;" : "=r"(r) : "f"(hi), "f"(lo));
    return r;
}
#define MMA_BF16(d0, d1, d2, d3, a0, a1, a2, a3, b0, b1)                                   \
    asm volatile(                                                                          \
        "mma.sync.aligned.m16n8k16.row.col.f32.bf16.bf16.f32 "                             \
        "{%0,%1,%2,%3},{%4,%5,%6,%7},{%8,%9},{%0,%1,%2,%3};"                               \
        : "+f"(d0), "+f"(d1), "+f"(d2), "+f"(d3)                                           \
        : "r"(a0), "r"(a1), "r"(a2), "r"(a3), "r"(b0), "r"(b1))
#define CPA16(dst, src) \
    asm volatile("cp.async.cg.shared.global [%0], [%1], 16;" :: "r"(dst), "l"(src))
#define CPA_COMMIT() asm volatile("cp.async.commit_group;")
#define CPA_WAIT1()  asm volatile("cp.async.wait_group 1;")

__device__ __forceinline__ void red4(float4* p, float4 v) {
    asm volatile("red.global.add.v4.f32 [%0], {%1,%2,%3,%4};"
                 :: "l"(p), "f"(v.x), "f"(v.y), "f"(v.z), "f"(v.w) : "memory");
}
__device__ __forceinline__ void red1(float* p, float v) {
    asm volatile("red.global.add.f32 [%0], %1;" :: "l"(p), "f"(v) : "memory");
}

// ---------------- setup: detect + pre1 + pre2 (block 0), zero (blocks 1+) ----------------
__global__ void setup_kernel(const int* __restrict__ ei,
                             const float* __restrict__ Wl, const float* __restrict__ W3,
                             const float* __restrict__ W5, const float* __restrict__ b3,
                             const float* __restrict__ b5, const float* __restrict__ bl,
                             const float* __restrict__ Wk, const float* __restrict__ bk) {
    int tid = threadIdx.x;
    if (blockIdx.x == 0) {
        if (tid == 0) {
            int all0 = 1;
            for (int i = 0; i < 16; i++)
                if (ei[2 * i + 1] != 0) all0 = 0;
            d_is64 = all0;
        }
        // pre1: Weff = Wl1*W3c + Wl2*W5c + Wl3 ; beff
        for (int idx = tid; idx < F * 36; idx += 256) {
            int o = idx / 36, k = idx % 36;
            if (k < F) {
                float w = Wl[o * 105 + 70 + k];
                for (int m = 0; m < F; m++) {
                    w = fmaf(Wl[o * 105 + m],      W3[(m * F + k) * 3 + 1], w);
                    w = fmaf(Wl[o * 105 + 35 + m], W5[(m * F + k) * 5 + 2], w);
                }
                d_Weff[o * F + k] = w;
            } else {
                float be = bl[o];
                for (int m = 0; m < F; m++) {
                    be = fmaf(Wl[o * 105 + m],      b3[m], be);
                    be = fmaf(Wl[o * 105 + 35 + m], b5[m], be);
                }
                d_beff[o] = be;
            }
        }
        __syncthreads();
        // pre2: Wc = (Weff @ Wk) * log2e/sqrt(F)
        const float CS = 1.4426950408889634f / sqrtf((float)F);
        for (int idx = tid; idx < F * 36; idx += 256) {
            int o = idx / 36, j = idx % 36;
            if (j < F) {
                float w = 0.f;
                for (int k = 0; k < F; k++) w = fmaf(d_Weff[o * F + k], Wk[k * F + j], w);
                d_Wc[o * F + j] = w * CS;
            } else {
                float b = d_beff[o];
                for (int k = 0; k < F; k++) b = fmaf(d_Weff[o * F + k], bk[k], b);
                d_bc[o] = b * CS;
            }
        }
    } else {
        int i = (blockIdx.x - 1) * 256 + tid;
        int stride = (gridDim.x - 1) * 256;
        float* af = (float*)d_agg4;
        for (int k = i; k < N_NODES * FP; k += stride) af[k] = 0.f;
        for (int k = i; k < N_NODES; k += stride) d_deg[k] = 0.f;
        for (int k = i; k < B_GRAPHS * FP; k += stride) d_g[k] = 0.f;
    }
}

// ---------------- proj: 32 nodes/block, 8 threads/node x 14 outputs ----------------
__global__ __launch_bounds__(256) void proj_kernel(const float* __restrict__ x,
                                                   const float* __restrict__ Wq,
                                                   const float* __restrict__ bq,
                                                   const float* __restrict__ Wv,
                                                   const float* __restrict__ bv) {
    // output index o: 0-34 = Q, 35-69 = V, 70-104 = Kn
    __shared__ __align__(16) float Wall[112 * 36];
    __shared__ float bsh[112];
    __shared__ __align__(16) float4 xs4[9][32];
    __shared__ float outS[32 * 113];
    int tid = threadIdx.x;
    int node0 = blockIdx.x * 32;

    for (int idx = tid; idx < 112 * 36; idx += 256) {
        int o = idx / 36, j = idx % 36;
        float v = 0.f;
        if (j < F && o < 105) {
            if (o < 35)      v = Wq[o * 35 + j];
            else if (o < 70) v = Wv[(o - 35) * 35 + j];
            else             v = d_Wc[(o - 70) * 35 + j];
        }
        Wall[idx] = v;
    }
    if (tid < 112) {
        float b = 0.f;
        if (tid < 35)       b = bq[tid];
        else if (tid < 70)  b = bv[tid - 35];
        else if (tid < 105) b = d_bc[tid - 70];
        bsh[tid] = b;
    }
    // stage x (contiguous global chunk), transposed into float4-friendly layout
    {
        float* xsf = (float*)xs4;
        for (int idx = tid; idx < 32 * 35; idx += 256) {
            int n = idx / 35, j = idx % 35;
            xsf[(j >> 2) * 128 + n * 4 + (j & 3)] = x[node0 * 35 + idx];
        }
        if (tid < 32) xsf[8 * 128 + tid * 4 + 3] = 0.f;  // pad j=35
    }
    __syncthreads();

    int c = tid >> 5;    // chunk (warp-uniform)
    int n = tid & 31;    // node
    float4 xv[9];
#pragma unroll
    for (int j4 = 0; j4 < 9; j4++) xv[j4] = xs4[j4][n];
    int o0 = c * 14;
    float acc[14];
#pragma unroll
    for (int k = 0; k < 14; k++) acc[k] = bsh[o0 + k];
#pragma unroll
    for (int j4 = 0; j4 < 9; j4++) {
        float4 xq = xv[j4];
#pragma unroll
        for (int k = 0; k < 14; k++) {
            const float4 wv = *(const float4*)&Wall[(o0 + k) * 36 + j4 * 4];
            acc[k] = fmaf(wv.x, xq.x, acc[k]);
            acc[k] = fmaf(wv.y, xq.y, acc[k]);
            acc[k] = fmaf(wv.z, xq.z, acc[k]);
            acc[k] = fmaf(wv.w, xq.w, acc[k]);
        }
    }
#pragma unroll
    for (int k = 0; k < 14; k++) outS[n * 113 + o0 + k] = acc[k];
    __syncthreads();

    // ---- stores ----
    // Kn bf16 [node][48] (24 words), from outputs 70+f, f<35
    for (int idx = tid; idx < 32 * 24; idx += 256) {
        int nn = idx / 24, wd = idx % 24;
        int f0 = 2 * wd;
        float v0 = (f0 < 35)     ? outS[nn * 113 + 70 + f0]     : 0.f;
        float v1 = (f0 + 1 < 35) ? outS[nn * 113 + 70 + f0 + 1] : 0.f;
        d_Kn32[(node0 + nn) * 24 + wd] = packbf(v1, v0);
    }
    // Qk bf16 (keys), from outputs f<35
    for (int idx = tid; idx < 32 * 24; idx += 256) {
        int nn = idx / 24, wd = idx % 24;
        int f0 = 2 * wd;
        float v0 = (f0 < 35)     ? outS[nn * 113 + f0]     : 0.f;
        float v1 = (f0 + 1 < 35) ? outS[nn * 113 + f0 + 1] : 0.f;
        d_Qk32[(node0 + nn) * 24 + wd] = packbf(v1, v0);
    }
    // V^T bf16 [feature][node]; row 35 = ones (for l)
    for (int idx = tid; idx < 36 * 32; idx += 256) {
        int f = idx >> 5, nn = idx & 31;
        float v = (f < 35) ? outS[nn * 113 + 35 + f] : 1.0f;
        d_VtT[f * QPAD + node0 + nn] = __bfloat16_as_ushort(__float2bfloat16(v));
    }
    // Vex exact f32 [node][40]
    for (int idx = tid; idx < 32 * 40; idx += 256) {
        int nn = idx / 40, f = idx % 40;
        d_Vex[(node0 + nn) * 40 + f] = (f < 35) ? outS[nn * 113 + 35 + f] : 0.f;
    }
}

// ---------------- bf16 flash attention: 128 q/CTA (8 warps), C->A fragment reuse ----------------
__global__ __launch_bounds__(256) void attn_kernel() {
    __shared__ __align__(16) uint32_t Ks[2][32 * 28];  // keys [32][56] bf16 per buf
    __shared__ __align__(16) uint32_t Vs[2][40 * 20];  // V^T [40][40] bf16 per buf

    int tid = threadIdx.x;
    int w = tid >> 5, lane = tid & 31;
    int gid = lane >> 2, tig = lane & 3;
    int qbase = blockIdx.x * 128 + w * 16;
    int split = blockIdx.y;

    // stationary A: 16 query rows of Kn, K=48 -> 3 chunks of 16
    uint32_t A[3][4];
#pragma unroll
    for (int kc = 0; kc < 3; kc++) {
        A[kc][0] = d_Kn32[(qbase + gid) * 24 + 8 * kc + tig];
        A[kc][1] = d_Kn32[(qbase + gid + 8) * 24 + 8 * kc + tig];
        A[kc][2] = d_Kn32[(qbase + gid) * 24 + 8 * kc + tig + 4];
        A[kc][3] = d_Kn32[(qbase + gid + 8) * 24 + 8 * kc + tig + 4];
    }
    float O[5][4];
#pragma unroll
    for (int nt = 0; nt < 5; nt++)
#pragma unroll
        for (int r = 0; r < 4; r++) O[nt][r] = 0.f;

    uint32_t ksb = (uint32_t)__cvta_generic_to_shared(&Ks[0][0]);
    uint32_t vsb = (uint32_t)__cvta_generic_to_shared(&Vs[0][0]);
    int kstart = split * (TILES_PER_SPLIT * KT);

    // stage tile 0 into buf 0
    for (int i = tid; i < 352; i += 256) {
        if (i < 192) {
            int r = i / 6, ch = i % 6;
            CPA16(ksb + r * 112 + ch * 16,
                  (const char*)d_Qk32 + (size_t)(kstart + r) * 96 + ch * 16);
        } else {
            int j = i - 192; int r = j / 4, ch = j % 4;
            CPA16(vsb + r * 80 + ch * 16,
                  (const char*)d_VtT + ((size_t)r * QPAD + kstart) * 2 + ch * 16);
        }
    }
    CPA_COMMIT();

    for (int t = 0; t < TILES_PER_SPLIT; t++) {
        int cur = t & 1;
        if (t < TILES_PER_SPLIT - 1) {
            int nb = cur ^ 1;
            int k0 = kstart + (t + 1) * KT;
            for (int i = tid; i < 352; i += 256) {
                if (i < 192) {
                    int r = i / 6, ch = i % 6;
                    CPA16(ksb + nb * 3584 + r * 112 + ch * 16,
                          (const char*)d_Qk32 + (size_t)(k0 + r) * 96 + ch * 16);
                } else {
                    int j = i - 192; int r = j / 4, ch = j % 4;
                    CPA16(vsb + nb * 3200 + r * 80 + ch * 16,
                          (const char*)d_VtT + ((size_t)r * QPAD + k0) * 2 + ch * 16);
                }
            }
        }
        CPA_COMMIT();
        CPA_WAIT1();
        __syncthreads();

        const uint32_t* K_ = Ks[cur];
        const uint32_t* V_ = Vs[cur];
        // ---- S = Kn(16x48) @ keys^T(48x32), exp2 into e ----
        float e[4][4];
#pragma unroll
        for (int nt = 0; nt < 4; nt++) {
            float S0 = 0.f, S1 = 0.f, S2 = 0.f, S3 = 0.f;
#pragma unroll
            for (int kc = 0; kc < 3; kc++) {
                uint32_t b0 = K_[(nt * 8 + gid) * 28 + 8 * kc + tig];
                uint32_t b1 = K_[(nt * 8 + gid) * 28 + 8 * kc + tig + 4];
                MMA_BF16(S0, S1, S2, S3, A[kc][0], A[kc][1], A[kc][2], A[kc][3], b0, b1);
            }
            e[nt][0] = ex2f(S0);
            e[nt][1] = ex2f(S1);
            e[nt][2] = ex2f(S2);
            e[nt][3] = ex2f(S3);
        }
        // ---- O += P(16x32) @ V(32x40); P frags packed directly from accumulators ----
#pragma unroll
        for (int kc = 0; kc < 2; kc++) {
            uint32_t a0 = packbf(e[2 * kc][1],     e[2 * kc][0]);
            uint32_t a1 = packbf(e[2 * kc][3],     e[2 * kc][2]);
            uint32_t a2 = packbf(e[2 * kc + 1][1], e[2 * kc + 1][0]);
            uint32_t a3 = packbf(e[2 * kc + 1][3], e[2 * kc + 1][2]);
#pragma unroll
            for (int nt = 0; nt < 5; nt++) {
                uint32_t b0 = V_[(nt * 8 + gid) * 20 + 8 * kc + tig];
                uint32_t b1 = V_[(nt * 8 + gid) * 20 + 8 * kc + tig + 4];
                MMA_BF16(O[nt][0], O[nt][1], O[nt][2], O[nt][3], a0, a1, a2, a3, b0, b1);
            }
        }
        __syncthreads();
    }

    float* Op = d_Opart[split];
    int q0r = qbase + gid, q1r = qbase + gid + 8;
#pragma unroll
    for (int nt = 0; nt < 5; nt++) {
        *(float2*)&Op[q0r * 40 + nt * 8 + 2 * tig] = make_float2(O[nt][0], O[nt][1]);
        *(float2*)&Op[q1r * 40 + nt * 8 + 2 * tig] = make_float2(O[nt][2], O[nt][3]);
    }
}

// ---------------- merge: h = relu(O/l + V), l = O[:,35] ----------------
__global__ void merge_kernel() {
    int i = blockIdx.x * blockDim.x + threadIdx.x;
    if (i >= N_NODES * F) return;
    int q = i / F, f = i - q * F;
    float O = d_Opart[0][q * 40 + f] + d_Opart[1][q * 40 + f] + d_Opart[2][q * 40 + f];
    float l = d_Opart[0][q * 40 + 35] + d_Opart[1][q * 40 + 35] + d_Opart[2][q * 40 + 35];
    float v = d_Vex[q * 40 + f];
    ((float*)d_h4)[q * FP + f] = fmaxf(fmaf(O, 1.0f / l, v), 0.f);
}

// ---------------- SAGE scatter: thread-per-edge, v4 reductions ----------------
__global__ void scatter_kernel(const int* __restrict__ ei) {
    int e = blockIdx.x * blockDim.x + threadIdx.x;
    if (e >= E_EDGES) return;
    int is64 = d_is64;
    int src = is64 ? ei[2 * e] : ei[e];
    int dst = is64 ? ei[2 * (E_EDGES + e)] : ei[E_EDGES + e];
    const float4* hs = d_h4 + src * 9;
    float4* ag = d_agg4 + dst * 9;
#pragma unroll
    for (int i = 0; i < 9; i++) red4(ag + i, hs[i]);
    red1(&d_deg[dst], 1.0f);
}

// ---------------- SAGE combine + fused global max pool ----------------
__global__ __launch_bounds__(128) void sage_kernel(const float* __restrict__ Wll,
                                                   const float* __restrict__ bll,
                                                   const float* __restrict__ Wlr,
                                                   const int* __restrict__ bat) {
    __shared__ float Wl_s[F * F], Wr_s[F * F], bl_s[F];
    __shared__ float hs[F][33], as[F][33];
    __shared__ float rd[32];
    __shared__ int bs[32];
    int tid = threadIdx.x;
    int n0 = blockIdx.x * 32;
    int is64 = d_is64;
    for (int w = tid; w < F * F; w += 128) {
        Wl_s[w] = Wll[w];
        Wr_s[w] = Wlr[w];
    }
    if (tid < F) bl_s[tid] = bll[tid];
    if (tid < 32) {
        rd[tid] = 1.0f / fmaxf(d_deg[n0 + tid], 1.0f);
        int node = n0 + tid;
        bs[tid] = is64 ? bat[2 * node] : bat[node];
    }
    const float* hf = (const float*)d_h4;
    const float* af = (const float*)d_agg4;
    for (int w = tid; w < 32 * F; w += 128) {
        int n = w / F, j = w % F;
        hs[j][n] = hf[(n0 + n) * FP + j];
        as[j][n] = af[(n0 + n) * FP + j];
    }
    __syncthreads();
    for (int w = tid; w < 32 * F; w += 128) {
        int n = w & 31, o = w >> 5;
        float a1 = 0.f, a2 = 0.f;
#pragma unroll
        for (int j = 0; j < F; j++) {
            a1 = fmaf(as[j][n], Wl_s[o * F + j], a1);
            a2 = fmaf(hs[j][n], Wr_s[o * F + j], a2);
        }
        float r = fmaf(a1, rd[n], bl_s[o]) + a2;
        r = fmaxf(r, 0.f);
        atomicMax((int*)&d_g[bs[n] * FP + o], __float_as_int(r));
    }
}

// ---------------- MLP head ----------------
__global__ __launch_bounds__(128) void mlp1_kernel(const float* __restrict__ Wg1,
                                                   const float* __restrict__ bg1) {
    __shared__ float gs[F][64];
    int tid = threadIdx.x;
    for (int w = tid; w < 64 * F; w += 128) {
        int b = w / F, d = w % F;
        gs[d][b] = d_g[b * FP + d];
    }
    __syncthreads();
    int j = blockIdx.x * 2 + (tid >> 6);
    int b = tid & 63;
    float acc = 0.f;
#pragma unroll
    for (int d = 0; d < F; d++) acc = fmaf(gs[d][b], __ldg(&Wg1[j * F + d]), acc);
    d_g1[b * H1 + j] = fmaxf(acc + bg1[j], 0.f);
}

__global__ void mlp2_kernel(const float* __restrict__ Wg2, const float* __restrict__ bg2) {
    int wid = (blockIdx.x * blockDim.x + threadIdx.x) >> 5;
    int lane = threadIdx.x & 31;
    if (wid >= B_GRAPHS * H2) return;
    int b = wid >> 7, j = wid & 127;
    float acc = 0.f;
    for (int d = lane; d < H1; d += 32)
        acc = fmaf(d_g1[b * H1 + d], Wg2[j * H1 + d], acc);
#pragma unroll
    for (int off = 16; off; off >>= 1) acc += __shfl_xor_sync(0xffffffffu, acc, off);
    if (lane == 0) d_g2[b * H2 + j] = acc + bg2[j];
}

__global__ void out_kernel(const float* __restrict__ Wo, const float* __restrict__ bo,
                           float* __restrict__ out) {
    int b = threadIdx.x;
    if (b < B_GRAPHS) {
        float acc = 0.f;
#pragma unroll
        for (int d = 0; d < H2; d++) acc = fmaf(d_g2[b * H2 + d], Wo[d], acc);
        out[b] = acc + bo[0];
    }
}

extern "C" void kernel_launch(void* const* d_in, const int* in_sizes, int n_in,
                              void* d_out, int out_size) {
    const float* x   = (const float*)d_in[0];
    const int*   ei  = (const int*)d_in[1];
    const int*   bat = (const int*)d_in[2];
    const float* Wq  = (const float*)d_in[3];
    const float* bq  = (const float*)d_in[4];
    const float* Wk  = (const float*)d_in[5];
    const float* bk  = (const float*)d_in[6];
    const float* Wv  = (const float*)d_in[7];
    const float* bv  = (const float*)d_in[8];
    const float* W3  = (const float*)d_in[9];
    const float* b3  = (const float*)d_in[10];
    const float* W5  = (const float*)d_in[11];
    const float* b5  = (const float*)d_in[12];
    const float* Wl  = (const float*)d_in[13];
    const float* bl  = (const float*)d_in[14];
    const float* Wll = (const float*)d_in[15];
    const float* bll = (const float*)d_in[16];
    const float* Wlr = (const float*)d_in[17];
    const float* Wg1 = (const float*)d_in[18];
    const float* bg1 = (const float*)d_in[19];
    const float* Wg2 = (const float*)d_in[20];
    const float* bg2 = (const float*)d_in[21];
    const float* Wo  = (const float*)d_in[22];
    const float* bo  = (const float*)d_in[23];
    float* out = (float*)d_out;

    setup_kernel<<<64, 256>>>(ei, Wl, W3, W5, b3, b5, bl, Wk, bk);
    proj_kernel<<<N_NODES / 32, 256>>>(x, Wq, bq, Wv, bv);
    attn_kernel<<<dim3(94, NSPLIT), 256>>>();
    merge_kernel<<<(N_NODES * F + 255) / 256, 256>>>();
    scatter_kernel<<<(E_EDGES + 255) / 256, 256>>>(ei);
    sage_kernel<<<N_NODES / 32, 128>>>(Wll, bll, Wlr, bat);
    mlp1_kernel<<<H1 / 2, 128>>>(Wg1, bg1);
    mlp2_kernel<<<B_GRAPHS * H2 / 4, 128>>>(Wg2, bg2);
    out_kernel<<<1, 64>>>(Wo, bo, out);
}

// round 8
// speedup vs baseline: 5.7373x; 1.0103x over previous
#include <cuda_runtime.h>
#include <cuda_bf16.h>
#include <math.h>
#include <stdint.h>

#define N_NODES 12000
#define F 35
#define FP 36
#define QPAD 12032
#define NSPLIT 3
#define KT 32
#define TILES_PER_SPLIT 125
#define E_EDGES 192000
#define B_GRAPHS 64
#define H1 1500
#define H2 128

// ---------------- scratch ----------------
// Kn/Qk: [12032][48] bf16 (24 words/row). VtT: [40][12032] bf16 transposed.
__device__ __align__(16) uint32_t d_Kn32[QPAD * 24];
__device__ __align__(16) uint32_t d_Qk32[QPAD * 24];
__device__ __align__(16) uint16_t d_VtT[40 * QPAD];
__device__ float d_Vex[QPAD * 40];
__device__ float d_Opart[NSPLIT][QPAD * 40];
__device__ float4 d_h4[N_NODES * 9];    // h, 36-stride
__device__ float4 d_agg4[N_NODES * 9];
__device__ float d_deg[N_NODES];
__device__ float d_Weff[F * F];
__device__ float d_beff[F];
__device__ float d_Wc[F * F];
__device__ float d_bc[F];
__device__ float d_g[B_GRAPHS * FP];
__device__ float d_g1[B_GRAPHS * H1];
__device__ float d_g2[B_GRAPHS * H2];
__device__ int d_is64;

__device__ __forceinline__ float ex2f(float x) {
    float r;
    asm("ex2.approx.f32 %0, %1;" : "=f"(r) : "f"(x));
    return r;
}
// pack {lo, hi} floats into bf16x2 (hi goes to upper half)
__device__ __forceinline__ uint32_t packbf(float hi, float lo) {
    uint32_t r;
    asm("cvt.rn.bf16x2.f32 %0, %1, %2;" : "=r"(r) : "f"(hi), "f"(lo));
    return r;
}
#define MMA_BF16(d0, d1, d2, d3, a0, a1, a2, a3, b0, b1)                                   \
    asm volatile(                                                                          \
        "mma.sync.aligned.m16n8k16.row.col.f32.bf16.bf16.f32 "                             \
        "{%0,%1,%2,%3},{%4,%5,%6,%7},{%8,%9},{%0,%1,%2,%3};"                               \
        : "+f"(d0), "+f"(d1), "+f"(d2), "+f"(d3)                                           \
        : "r"(a0), "r"(a1), "r"(a2), "r"(a3), "r"(b0), "r"(b1))
#define CPA16(dst, src) \
    asm volatile("cp.async.cg.shared.global [%0], [%1], 16;" :: "r"(dst), "l"(src))
#define CPA_COMMIT() asm volatile("cp.async.commit_group;")
#define CPA_WAIT1()  asm volatile("cp.async.wait_group 1;")

__device__ __forceinline__ void red4(float4* p, float4 v) {
    asm volatile("red.global.add.v4.f32 [%0], {%1,%2,%3,%4};"
                 :: "l"(p), "f"(v.x), "f"(v.y), "f"(v.z), "f"(v.w) : "memory");
}
__device__ __forceinline__ void red1(float* p, float v) {
    asm volatile("red.global.add.f32 [%0], %1;" :: "l"(p), "f"(v) : "memory");
}

// ---------------- setup: detect + pre1 + pre2 (block 0), zero (blocks 1+) ----------------
__global__ void setup_kernel(const int* __restrict__ ei,
                             const float* __restrict__ Wl, const float* __restrict__ W3,
                             const float* __restrict__ W5, const float* __restrict__ b3,
                             const float* __restrict__ b5, const float* __restrict__ bl,
                             const float* __restrict__ Wk, const float* __restrict__ bk) {
    int tid = threadIdx.x;
    if (blockIdx.x == 0) {
        if (tid == 0) {
            int all0 = 1;
            for (int i = 0; i < 16; i++)
                if (ei[2 * i + 1] != 0) all0 = 0;
            d_is64 = all0;
        }
        // pre1: Weff = Wl1*W3c + Wl2*W5c + Wl3 ; beff
        for (int idx = tid; idx < F * 36; idx += 256) {
            int o = idx / 36, k = idx % 36;
            if (k < F) {
                float w = Wl[o * 105 + 70 + k];
                for (int m = 0; m < F; m++) {
                    w = fmaf(Wl[o * 105 + m],      W3[(m * F + k) * 3 + 1], w);
                    w = fmaf(Wl[o * 105 + 35 + m], W5[(m * F + k) * 5 + 2], w);
                }
                d_Weff[o * F + k] = w;
            } else {
                float be = bl[o];
                for (int m = 0; m < F; m++) {
                    be = fmaf(Wl[o * 105 + m],      b3[m], be);
                    be = fmaf(Wl[o * 105 + 35 + m], b5[m], be);
                }
                d_beff[o] = be;
            }
        }
        __syncthreads();
        // pre2: Wc = (Weff @ Wk) * log2e/sqrt(F)
        const float CS = 1.4426950408889634f / sqrtf((float)F);
        for (int idx = tid; idx < F * 36; idx += 256) {
            int o = idx / 36, j = idx % 36;
            if (j < F) {
                float w = 0.f;
                for (int k = 0; k < F; k++) w = fmaf(d_Weff[o * F + k], Wk[k * F + j], w);
                d_Wc[o * F + j] = w * CS;
            } else {
                float b = d_beff[o];
                for (int k = 0; k < F; k++) b = fmaf(d_Weff[o * F + k], bk[k], b);
                d_bc[o] = b * CS;
            }
        }
    } else {
        int i = (blockIdx.x - 1) * 256 + tid;
        int stride = (gridDim.x - 1) * 256;
        float* af = (float*)d_agg4;
        for (int k = i; k < N_NODES * FP; k += stride) af[k] = 0.f;
        for (int k = i; k < N_NODES; k += stride) d_deg[k] = 0.f;
        for (int k = i; k < B_GRAPHS * FP; k += stride) d_g[k] = 0.f;
    }
}

// ---------------- proj: 32 nodes/block, 8 threads/node x 14 outputs ----------------
__global__ __launch_bounds__(256) void proj_kernel(const float* __restrict__ x,
                                                   const float* __restrict__ Wq,
                                                   const float* __restrict__ bq,
                                                   const float* __restrict__ Wv,
                                                   const float* __restrict__ bv) {
    // output index o: 0-34 = Q, 35-69 = V, 70-104 = Kn
    __shared__ __align__(16) float Wall[112 * 36];
    __shared__ float bsh[112];
    __shared__ __align__(16) float4 xs4[9][32];
    __shared__ float outS[32 * 113];
    int tid = threadIdx.x;
    int node0 = blockIdx.x * 32;

    for (int idx = tid; idx < 112 * 36; idx += 256) {
        int o = idx / 36, j = idx % 36;
        float v = 0.f;
        if (j < F && o < 105) {
            if (o < 35)      v = Wq[o * 35 + j];
            else if (o < 70) v = Wv[(o - 35) * 35 + j];
            else             v = d_Wc[(o - 70) * 35 + j];
        }
        Wall[idx] = v;
    }
    if (tid < 112) {
        float b = 0.f;
        if (tid < 35)       b = bq[tid];
        else if (tid < 70)  b = bv[tid - 35];
        else if (tid < 105) b = d_bc[tid - 70];
        bsh[tid] = b;
    }
    // stage x (contiguous global chunk), transposed into float4-friendly layout
    {
        float* xsf = (float*)xs4;
        for (int idx = tid; idx < 32 * 35; idx += 256) {
            int n = idx / 35, j = idx % 35;
            xsf[(j >> 2) * 128 + n * 4 + (j & 3)] = x[node0 * 35 + idx];
        }
        if (tid < 32) xsf[8 * 128 + tid * 4 + 3] = 0.f;  // pad j=35
    }
    __syncthreads();

    int c = tid >> 5;    // chunk (warp-uniform)
    int n = tid & 31;    // node
    float4 xv[9];
#pragma unroll
    for (int j4 = 0; j4 < 9; j4++) xv[j4] = xs4[j4][n];
    int o0 = c * 14;
    float acc[14];
#pragma unroll
    for (int k = 0; k < 14; k++) acc[k] = bsh[o0 + k];
#pragma unroll
    for (int j4 = 0; j4 < 9; j4++) {
        float4 xq = xv[j4];
#pragma unroll
        for (int k = 0; k < 14; k++) {
            const float4 wv = *(const float4*)&Wall[(o0 + k) * 36 + j4 * 4];
            acc[k] = fmaf(wv.x, xq.x, acc[k]);
            acc[k] = fmaf(wv.y, xq.y, acc[k]);
            acc[k] = fmaf(wv.z, xq.z, acc[k]);
            acc[k] = fmaf(wv.w, xq.w, acc[k]);
        }
    }
#pragma unroll
    for (int k = 0; k < 14; k++) outS[n * 113 + o0 + k] = acc[k];
    __syncthreads();

    // ---- stores ----
    // Kn bf16 [node][48] (24 words), from outputs 70+f, f<35
    for (int idx = tid; idx < 32 * 24; idx += 256) {
        int nn = idx / 24, wd = idx % 24;
        int f0 = 2 * wd;
        float v0 = (f0 < 35)     ? outS[nn * 113 + 70 + f0]     : 0.f;
        float v1 = (f0 + 1 < 35) ? outS[nn * 113 + 70 + f0 + 1] : 0.f;
        d_Kn32[(node0 + nn) * 24 + wd] = packbf(v1, v0);
    }
    // Qk bf16 (keys), from outputs f<35
    for (int idx = tid; idx < 32 * 24; idx += 256) {
        int nn = idx / 24, wd = idx % 24;
        int f0 = 2 * wd;
        float v0 = (f0 < 35)     ? outS[nn * 113 + f0]     : 0.f;
        float v1 = (f0 + 1 < 35) ? outS[nn * 113 + f0 + 1] : 0.f;
        d_Qk32[(node0 + nn) * 24 + wd] = packbf(v1, v0);
    }
    // V^T bf16 [feature][node]; row 35 = ones (for l)
    for (int idx = tid; idx < 36 * 32; idx += 256) {
        int f = idx >> 5, nn = idx & 31;
        float v = (f < 35) ? outS[nn * 113 + 35 + f] : 1.0f;
        d_VtT[f * QPAD + node0 + nn] = __bfloat16_as_ushort(__float2bfloat16(v));
    }
    // Vex exact f32 [node][40]
    for (int idx = tid; idx < 32 * 40; idx += 256) {
        int nn = idx / 40, f = idx % 40;
        d_Vex[(node0 + nn) * 40 + f] = (f < 35) ? outS[nn * 113 + 35 + f] : 0.f;
    }
}

// ---------------- bf16 flash attention: 128 q/CTA (8 warps), C->A fragment reuse ----------------
__global__ __launch_bounds__(256) void attn_kernel() {
    __shared__ __align__(16) uint32_t Ks[2][32 * 28];  // keys [32][56] bf16 per buf
    __shared__ __align__(16) uint32_t Vs[2][40 * 20];  // V^T [40][40] bf16 per buf

    int tid = threadIdx.x;
    int w = tid >> 5, lane = tid & 31;
    int gid = lane >> 2, tig = lane & 3;
    int qbase = blockIdx.x * 128 + w * 16;
    int split = blockIdx.y;

    // stationary A: 16 query rows of Kn, K=48 -> 3 chunks of 16
    uint32_t A[3][4];
#pragma unroll
    for (int kc = 0; kc < 3; kc++) {
        A[kc][0] = d_Kn32[(qbase + gid) * 24 + 8 * kc + tig];
        A[kc][1] = d_Kn32[(qbase + gid + 8) * 24 + 8 * kc + tig];
        A[kc][2] = d_Kn32[(qbase + gid) * 24 + 8 * kc + tig + 4];
        A[kc][3] = d_Kn32[(qbase + gid + 8) * 24 + 8 * kc + tig + 4];
    }
    float O[5][4];
#pragma unroll
    for (int nt = 0; nt < 5; nt++)
#pragma unroll
        for (int r = 0; r < 4; r++) O[nt][r] = 0.f;

    uint32_t ksb = (uint32_t)__cvta_generic_to_shared(&Ks[0][0]);
    uint32_t vsb = (uint32_t)__cvta_generic_to_shared(&Vs[0][0]);
    int kstart = split * (TILES_PER_SPLIT * KT);

    // stage tile 0 into buf 0
    for (int i = tid; i < 352; i += 256) {
        if (i < 192) {
            int r = i / 6, ch = i % 6;
            CPA16(ksb + r * 112 + ch * 16,
                  (const char*)d_Qk32 + (size_t)(kstart + r) * 96 + ch * 16);
        } else {
            int j = i - 192; int r = j / 4, ch = j % 4;
            CPA16(vsb + r * 80 + ch * 16,
                  (const char*)d_VtT + ((size_t)r * QPAD + kstart) * 2 + ch * 16);
        }
    }
    CPA_COMMIT();

    for (int t = 0; t < TILES_PER_SPLIT; t++) {
        int cur = t & 1;
        if (t < TILES_PER_SPLIT - 1) {
            int nb = cur ^ 1;
            int k0 = kstart + (t + 1) * KT;
            for (int i = tid; i < 352; i += 256) {
                if (i < 192) {
                    int r = i / 6, ch = i % 6;
                    CPA16(ksb + nb * 3584 + r * 112 + ch * 16,
                          (const char*)d_Qk32 + (size_t)(k0 + r) * 96 + ch * 16);
                } else {
                    int j = i - 192; int r = j / 4, ch = j % 4;
                    CPA16(vsb + nb * 3200 + r * 80 + ch * 16,
                          (const char*)d_VtT + ((size_t)r * QPAD + k0) * 2 + ch * 16);
                }
            }
        }
        CPA_COMMIT();
        CPA_WAIT1();
        __syncthreads();

        const uint32_t* K_ = Ks[cur];
        const uint32_t* V_ = Vs[cur];
        // ---- S = Kn(16x48) @ keys^T(48x32), exp2 into e ----
        float e[4][4];
#pragma unroll
        for (int nt = 0; nt < 4; nt++) {
            float S0 = 0.f, S1 = 0.f, S2 = 0.f, S3 = 0.f;
#pragma unroll
            for (int kc = 0; kc < 3; kc++) {
                uint32_t b0 = K_[(nt * 8 + gid) * 28 + 8 * kc + tig];
                uint32_t b1 = K_[(nt * 8 + gid) * 28 + 8 * kc + tig + 4];
                MMA_BF16(S0, S1, S2, S3, A[kc][0], A[kc][1], A[kc][2], A[kc][3], b0, b1);
            }
            e[nt][0] = ex2f(S0);
            e[nt][1] = ex2f(S1);
            e[nt][2] = ex2f(S2);
            e[nt][3] = ex2f(S3);
        }
        // ---- O += P(16x32) @ V(32x40); P frags packed directly from accumulators ----
#pragma unroll
        for (int kc = 0; kc < 2; kc++) {
            uint32_t a0 = packbf(e[2 * kc][1],     e[2 * kc][0]);
            uint32_t a1 = packbf(e[2 * kc][3],     e[2 * kc][2]);
            uint32_t a2 = packbf(e[2 * kc + 1][1], e[2 * kc + 1][0]);
            uint32_t a3 = packbf(e[2 * kc + 1][3], e[2 * kc + 1][2]);
#pragma unroll
            for (int nt = 0; nt < 5; nt++) {
                uint32_t b0 = V_[(nt * 8 + gid) * 20 + 8 * kc + tig];
                uint32_t b1 = V_[(nt * 8 + gid) * 20 + 8 * kc + tig + 4];
                MMA_BF16(O[nt][0], O[nt][1], O[nt][2], O[nt][3], a0, a1, a2, a3, b0, b1);
            }
        }
        __syncthreads();
    }

    float* Op = d_Opart[split];
    int q0r = qbase + gid, q1r = qbase + gid + 8;
#pragma unroll
    for (int nt = 0; nt < 5; nt++) {
        *(float2*)&Op[q0r * 40 + nt * 8 + 2 * tig] = make_float2(O[nt][0], O[nt][1]);
        *(float2*)&Op[q1r * 40 + nt * 8 + 2 * tig] = make_float2(O[nt][2], O[nt][3]);
    }
}

// ---------------- merge: h = relu(O/l + V), l = O[:,35] ----------------
__global__ void merge_kernel() {
    int i = blockIdx.x * blockDim.x + threadIdx.x;
    if (i >= N_NODES * F) return;
    int q = i / F, f = i - q * F;
    float O = d_Opart[0][q * 40 + f] + d_Opart[1][q * 40 + f] + d_Opart[2][q * 40 + f];
    float l = d_Opart[0][q * 40 + 35] + d_Opart[1][q * 40 + 35] + d_Opart[2][q * 40 + 35];
    float v = d_Vex[q * 40 + f];
    ((float*)d_h4)[q * FP + f] = fmaxf(fmaf(O, 1.0f / l, v), 0.f);
}

// ---------------- SAGE scatter: thread-per-edge, v4 reductions ----------------
__global__ void scatter_kernel(const int* __restrict__ ei) {
    int e = blockIdx.x * blockDim.x + threadIdx.x;
    if (e >= E_EDGES) return;
    int is64 = d_is64;
    int src = is64 ? ei[2 * e] : ei[e];
    int dst = is64 ? ei[2 * (E_EDGES + e)] : ei[E_EDGES + e];
    const float4* hs = d_h4 + src * 9;
    float4* ag = d_agg4 + dst * 9;
#pragma unroll
    for (int i = 0; i < 9; i++) red4(ag + i, hs[i]);
    red1(&d_deg[dst], 1.0f);
}

// ---------------- SAGE combine + fused global max pool ----------------
__global__ __launch_bounds__(128) void sage_kernel(const float* __restrict__ Wll,
                                                   const float* __restrict__ bll,
                                                   const float* __restrict__ Wlr,
                                                   const int* __restrict__ bat) {
    __shared__ float Wl_s[F * F], Wr_s[F * F], bl_s[F];
    __shared__ float hs[F][33], as[F][33];
    __shared__ float rd[32];
    __shared__ int bs[32];
    int tid = threadIdx.x;
    int n0 = blockIdx.x * 32;
    int is64 = d_is64;
    for (int w = tid; w < F * F; w += 128) {
        Wl_s[w] = Wll[w];
        Wr_s[w] = Wlr[w];
    }
    if (tid < F) bl_s[tid] = bll[tid];
    if (tid < 32) {
        rd[tid] = 1.0f / fmaxf(d_deg[n0 + tid], 1.0f);
        int node = n0 + tid;
        bs[tid] = is64 ? bat[2 * node] : bat[node];
    }
    const float* hf = (const float*)d_h4;
    const float* af = (const float*)d_agg4;
    for (int w = tid; w < 32 * F; w += 128) {
        int n = w / F, j = w % F;
        hs[j][n] = hf[(n0 + n) * FP + j];
        as[j][n] = af[(n0 + n) * FP + j];
    }
    __syncthreads();
    for (int w = tid; w < 32 * F; w += 128) {
        int n = w & 31, o = w >> 5;
        float a1 = 0.f, a2 = 0.f;
#pragma unroll
        for (int j = 0; j < F; j++) {
            a1 = fmaf(as[j][n], Wl_s[o * F + j], a1);
            a2 = fmaf(hs[j][n], Wr_s[o * F + j], a2);
        }
        float r = fmaf(a1, rd[n], bl_s[o]) + a2;
        r = fmaxf(r, 0.f);
        atomicMax((int*)&d_g[bs[n] * FP + o], __float_as_int(r));
    }
}

// ---------------- MLP head ----------------
__global__ __launch_bounds__(128) void mlp1_kernel(const float* __restrict__ Wg1,
                                                   const float* __restrict__ bg1) {
    __shared__ float gs[F][64];
    int tid = threadIdx.x;
    for (int w = tid; w < 64 * F; w += 128) {
        int b = w / F, d = w % F;
        gs[d][b] = d_g[b * FP + d];
    }
    __syncthreads();
    int j = blockIdx.x * 2 + (tid >> 6);
    int b = tid & 63;
    float acc = 0.f;
#pragma unroll
    for (int d = 0; d < F; d++) acc = fmaf(gs[d][b], __ldg(&Wg1[j * F + d]), acc);
    d_g1[b * H1 + j] = fmaxf(acc + bg1[j], 0.f);
}

__global__ void mlp2_kernel(const float* __restrict__ Wg2, const float* __restrict__ bg2) {
    int wid = (blockIdx.x * blockDim.x + threadIdx.x) >> 5;
    int lane = threadIdx.x & 31;
    if (wid >= B_GRAPHS * H2) return;
    int b = wid >> 7, j = wid & 127;
    float acc = 0.f;
    for (int d = lane; d < H1; d += 32)
        acc = fmaf(d_g1[b * H1 + d], Wg2[j * H1 + d], acc);
#pragma unroll
    for (int off = 16; off; off >>= 1) acc += __shfl_xor_sync(0xffffffffu, acc, off);
    if (lane == 0) d_g2[b * H2 + j] = acc + bg2[j];
}

__global__ void out_kernel(const float* __restrict__ Wo, const float* __restrict__ bo,
                           float* __restrict__ out) {
    int b = threadIdx.x;
    if (b < B_GRAPHS) {
        float acc = 0.f;
#pragma unroll
        for (int d = 0; d < H2; d++) acc = fmaf(d_g2[b * H2 + d], Wo[d], acc);
        out[b] = acc + bo[0];
    }
}

extern "C" void kernel_launch(void* const* d_in, const int* in_sizes, int n_in,
                              void* d_out, int out_size) {
    const float* x   = (const float*)d_in[0];
    const int*   ei  = (const int*)d_in[1];
    const int*   bat = (const int*)d_in[2];
    const float* Wq  = (const float*)d_in[3];
    const float* bq  = (const float*)d_in[4];
    const float* Wk  = (const float*)d_in[5];
    const float* bk  = (const float*)d_in[6];
    const float* Wv  = (const float*)d_in[7];
    const float* bv  = (const float*)d_in[8];
    const float* W3  = (const float*)d_in[9];
    const float* b3  = (const float*)d_in[10];
    const float* W5  = (const float*)d_in[11];
    const float* b5  = (const float*)d_in[12];
    const float* Wl  = (const float*)d_in[13];
    const float* bl  = (const float*)d_in[14];
    const float* Wll = (const float*)d_in[15];
    const float* bll = (const float*)d_in[16];
    const float* Wlr = (const float*)d_in[17];
    const float* Wg1 = (const float*)d_in[18];
    const float* bg1 = (const float*)d_in[19];
    const float* Wg2 = (const float*)d_in[20];
    const float* bg2 = (const float*)d_in[21];
    const float* Wo  = (const float*)d_in[22];
    const float* bo  = (const float*)d_in[23];
    float* out = (float*)d_out;

    setup_kernel<<<64, 256>>>(ei, Wl, W3, W5, b3, b5, bl, Wk, bk);
    proj_kernel<<<N_NODES / 32, 256>>>(x, Wq, bq, Wv, bv);
    attn_kernel<<<dim3(94, NSPLIT), 256>>>();
    merge_kernel<<<(N_NODES * F + 255) / 256, 256>>>();
    scatter_kernel<<<(E_EDGES + 255) / 256, 256>>>(ei);
    sage_kernel<<<N_NODES / 32, 128>>>(Wll, bll, Wlr, bat);
    mlp1_kernel<<<H1 / 2, 128>>>(Wg1, bg1);
    mlp2_kernel<<<B_GRAPHS * H2 / 4, 128>>>(Wg2, bg2);
    out_kernel<<<1, 64>>>(Wo, bo, out);
}

// round 9
// speedup vs baseline: 5.9710x; 1.0407x over previous
#include <cuda_runtime.h>
#include <cuda_bf16.h>
#include <math.h>
#include <stdint.h>

#define N_NODES 12000
#define F 35
#define FP 36
#define QPAD 12032
#define NSPLIT 3
#define KT 64
#define NTILES 188          // 188 * 64 = 12032 padded keys
#define E_EDGES 192000
#define B_GRAPHS 64
#define H1 1500
#define H2 128

// ---------------- scratch ----------------
__device__ __align__(16) uint32_t d_Kn32[QPAD * 24];  // queries bf16 [row][48]
__device__ __align__(16) uint32_t d_Qk32[QPAD * 24];  // keys bf16
__device__ __align__(16) uint16_t d_VtT[40 * QPAD];   // V^T bf16; row35=ones, pad cols=0
__device__ float d_Vex[QPAD * 40];
__device__ float d_Opart[NSPLIT][QPAD * 40];
__device__ float4 d_h4[N_NODES * 9];    // h, 36-stride; elem35 = 1.0 (deg carrier)
__device__ float4 d_agg4[N_NODES * 9];  // agg; elem35 accumulates degree
__device__ float d_Weff[F * F];
__device__ float d_beff[F];
__device__ float d_Wc[F * F];
__device__ float d_bc[F];
__device__ float d_g[B_GRAPHS * FP];
__device__ float d_g1[B_GRAPHS * H1];
__device__ float d_g2[B_GRAPHS * H2];
__device__ int d_is64;

__device__ __forceinline__ float ex2f(float x) {
    float r;
    asm("ex2.approx.f32 %0, %1;" : "=f"(r) : "f"(x));
    return r;
}
__device__ __forceinline__ uint32_t packbf(float hi, float lo) {
    uint32_t r;
    asm("cvt.rn.bf16x2.f32 %0, %1, %2;" : "=r"(r) : "f"(hi), "f"(lo));
    return r;
}
#define MMA_BF16(d0, d1, d2, d3, a0, a1, a2, a3, b0, b1)                                   \
    asm volatile(                                                                          \
        "mma.sync.aligned.m16n8k16.row.col.f32.bf16.bf16.f32 "                             \
        "{%0,%1,%2,%3},{%4,%5,%6,%7},{%8,%9},{%0,%1,%2,%3};"                               \
        : "+f"(d0), "+f"(d1), "+f"(d2), "+f"(d3)                                           \
        : "r"(a0), "r"(a1), "r"(a2), "r"(a3), "r"(b0), "r"(b1))
#define CPA16(dst, src) \
    asm volatile("cp.async.cg.shared.global [%0], [%1], 16;" :: "r"(dst), "l"(src))
#define CPA_COMMIT() asm volatile("cp.async.commit_group;")
#define CPA_WAIT1()  asm volatile("cp.async.wait_group 1;")

__device__ __forceinline__ void red4(float4* p, float4 v) {
    asm volatile("red.global.add.v4.f32 [%0], {%1,%2,%3,%4};"
                 :: "l"(p), "f"(v.x), "f"(v.y), "f"(v.z), "f"(v.w) : "memory");
}

// ---------------- setup: detect + pre1 + pre2 (block 0), zero (blocks 1+) ----------------
__global__ void setup_kernel(const int* __restrict__ ei,
                             const float* __restrict__ Wl, const float* __restrict__ W3,
                             const float* __restrict__ W5, const float* __restrict__ b3,
                             const float* __restrict__ b5, const float* __restrict__ bl,
                             const float* __restrict__ Wk, const float* __restrict__ bk) {
    int tid = threadIdx.x;
    if (blockIdx.x == 0) {
        if (tid == 0) {
            int all0 = 1;
            for (int i = 0; i < 16; i++)
                if (ei[2 * i + 1] != 0) all0 = 0;
            d_is64 = all0;
        }
        for (int idx = tid; idx < F * 36; idx += 256) {
            int o = idx / 36, k = idx % 36;
            if (k < F) {
                float w = Wl[o * 105 + 70 + k];
                for (int m = 0; m < F; m++) {
                    w = fmaf(Wl[o * 105 + m],      W3[(m * F + k) * 3 + 1], w);
                    w = fmaf(Wl[o * 105 + 35 + m], W5[(m * F + k) * 5 + 2], w);
                }
                d_Weff[o * F + k] = w;
            } else {
                float be = bl[o];
                for (int m = 0; m < F; m++) {
                    be = fmaf(Wl[o * 105 + m],      b3[m], be);
                    be = fmaf(Wl[o * 105 + 35 + m], b5[m], be);
                }
                d_beff[o] = be;
            }
        }
        __syncthreads();
        const float CS = 1.4426950408889634f / sqrtf((float)F);
        for (int idx = tid; idx < F * 36; idx += 256) {
            int o = idx / 36, j = idx % 36;
            if (j < F) {
                float w = 0.f;
                for (int k = 0; k < F; k++) w = fmaf(d_Weff[o * F + k], Wk[k * F + j], w);
                d_Wc[o * F + j] = w * CS;
            } else {
                float b = d_beff[o];
                for (int k = 0; k < F; k++) b = fmaf(d_Weff[o * F + k], bk[k], b);
                d_bc[o] = b * CS;
            }
        }
    } else {
        int i = (blockIdx.x - 1) * 256 + tid;
        int stride = (gridDim.x - 1) * 256;
        float* af = (float*)d_agg4;
        for (int k = i; k < N_NODES * FP; k += stride) af[k] = 0.f;
        for (int k = i; k < B_GRAPHS * FP; k += stride) d_g[k] = 0.f;
    }
}

// ---------------- proj: 32 nodes/block, 8 threads/node x 14 outputs ----------------
__global__ __launch_bounds__(256) void proj_kernel(const float* __restrict__ x,
                                                   const float* __restrict__ Wq,
                                                   const float* __restrict__ bq,
                                                   const float* __restrict__ Wv,
                                                   const float* __restrict__ bv) {
    __shared__ __align__(16) float Wall[112 * 36];
    __shared__ float bsh[112];
    __shared__ __align__(16) float4 xs4[9][32];
    __shared__ float outS[32 * 113];
    int tid = threadIdx.x;
    int node0 = blockIdx.x * 32;

    for (int idx = tid; idx < 112 * 36; idx += 256) {
        int o = idx / 36, j = idx % 36;
        float v = 0.f;
        if (j < F && o < 105) {
            if (o < 35)      v = Wq[o * 35 + j];
            else if (o < 70) v = Wv[(o - 35) * 35 + j];
            else             v = d_Wc[(o - 70) * 35 + j];
        }
        Wall[idx] = v;
    }
    if (tid < 112) {
        float b = 0.f;
        if (tid < 35)       b = bq[tid];
        else if (tid < 70)  b = bv[tid - 35];
        else if (tid < 105) b = d_bc[tid - 70];
        bsh[tid] = b;
    }
    {
        float* xsf = (float*)xs4;
        for (int idx = tid; idx < 32 * 35; idx += 256) {
            int n = idx / 35, j = idx % 35;
            float v = (node0 + n < N_NODES) ? x[node0 * 35 + idx] : 0.f;
            xsf[(j >> 2) * 128 + n * 4 + (j & 3)] = v;
        }
        if (tid < 32) xsf[8 * 128 + tid * 4 + 3] = 0.f;
    }
    __syncthreads();

    int c = tid >> 5;
    int n = tid & 31;
    float4 xv[9];
#pragma unroll
    for (int j4 = 0; j4 < 9; j4++) xv[j4] = xs4[j4][n];
    int o0 = c * 14;
    float acc[14];
#pragma unroll
    for (int k = 0; k < 14; k++) acc[k] = bsh[o0 + k];
#pragma unroll
    for (int j4 = 0; j4 < 9; j4++) {
        float4 xq = xv[j4];
#pragma unroll
        for (int k = 0; k < 14; k++) {
            const float4 wv = *(const float4*)&Wall[(o0 + k) * 36 + j4 * 4];
            acc[k] = fmaf(wv.x, xq.x, acc[k]);
            acc[k] = fmaf(wv.y, xq.y, acc[k]);
            acc[k] = fmaf(wv.z, xq.z, acc[k]);
            acc[k] = fmaf(wv.w, xq.w, acc[k]);
        }
    }
#pragma unroll
    for (int k = 0; k < 14; k++) outS[n * 113 + o0 + k] = acc[k];
    __syncthreads();

    // Kn bf16 (queries); pad nodes -> 0
    for (int idx = tid; idx < 32 * 24; idx += 256) {
        int nn = idx / 24, wd = idx % 24;
        int real = (node0 + nn < N_NODES);
        int f0 = 2 * wd;
        float v0 = (real && f0 < 35)     ? outS[nn * 113 + 70 + f0]     : 0.f;
        float v1 = (real && f0 + 1 < 35) ? outS[nn * 113 + 70 + f0 + 1] : 0.f;
        d_Kn32[(node0 + nn) * 24 + wd] = packbf(v1, v0);
    }
    // Qk bf16 (keys); pad -> 0
    for (int idx = tid; idx < 32 * 24; idx += 256) {
        int nn = idx / 24, wd = idx % 24;
        int real = (node0 + nn < N_NODES);
        int f0 = 2 * wd;
        float v0 = (real && f0 < 35)     ? outS[nn * 113 + f0]     : 0.f;
        float v1 = (real && f0 + 1 < 35) ? outS[nn * 113 + f0 + 1] : 0.f;
        d_Qk32[(node0 + nn) * 24 + wd] = packbf(v1, v0);
    }
    // V^T bf16; row 35 = ones for real nodes, 0 for pad (kills pad-key contributions)
    for (int idx = tid; idx < 36 * 32; idx += 256) {
        int f = idx >> 5, nn = idx & 31;
        int real = (node0 + nn < N_NODES);
        float v = real ? ((f < 35) ? outS[nn * 113 + 35 + f] : 1.0f) : 0.f;
        d_VtT[f * QPAD + node0 + nn] = __bfloat16_as_ushort(__float2bfloat16(v));
    }
    // Vex exact f32
    for (int idx = tid; idx < 32 * 40; idx += 256) {
        int nn = idx / 40, f = idx % 40;
        int real = (node0 + nn < N_NODES);
        d_Vex[(node0 + nn) * 40 + f] = (real && f < 35) ? outS[nn * 113 + 35 + f] : 0.f;
    }
}

// ---------------- bf16 flash attention: 256 q/CTA, 32 q/warp, 64-key tiles ----------------
__global__ __launch_bounds__(256) void attn_kernel() {
    __shared__ __align__(16) uint32_t Ks[2][KT * 28];  // keys [64][56] bf16
    __shared__ __align__(16) uint32_t Vs[2][40 * 36];  // V^T [40][72] bf16

    int tid = threadIdx.x;
    int w = tid >> 5, lane = tid & 31;
    int gid = lane >> 2, tig = lane & 3;
    int qbase = blockIdx.x * 256 + w * 32;
    int split = blockIdx.y;
    int t0 = split * 63;
    int tend = (split == 2) ? NTILES : t0 + 63;

    // stationary A: 2 halves x 16 query rows, K=48 -> 3 chunks
    uint32_t A[2][3][4];
#pragma unroll
    for (int h = 0; h < 2; h++)
#pragma unroll
        for (int kc = 0; kc < 3; kc++) {
            int r0 = qbase + h * 16 + gid;
            A[h][kc][0] = d_Kn32[r0 * 24 + 8 * kc + tig];
            A[h][kc][1] = d_Kn32[(r0 + 8) * 24 + 8 * kc + tig];
            A[h][kc][2] = d_Kn32[r0 * 24 + 8 * kc + tig + 4];
            A[h][kc][3] = d_Kn32[(r0 + 8) * 24 + 8 * kc + tig + 4];
        }
    float O[2][5][4];
#pragma unroll
    for (int h = 0; h < 2; h++)
#pragma unroll
        for (int nt = 0; nt < 5; nt++)
#pragma unroll
            for (int r = 0; r < 4; r++) O[h][nt][r] = 0.f;

    uint32_t ksb = (uint32_t)__cvta_generic_to_shared(&Ks[0][0]);
    uint32_t vsb = (uint32_t)__cvta_generic_to_shared(&Vs[0][0]);

    // stage tile t0 into buf 0: K 64 rows x 6 chunks = 384, V 40 rows x 8 chunks = 320
    {
        int k0 = t0 * KT;
        for (int i = tid; i < 704; i += 256) {
            if (i < 384) {
                int r = i / 6, ch = i % 6;
                CPA16(ksb + r * 112 + ch * 16,
                      (const char*)d_Qk32 + (size_t)(k0 + r) * 96 + ch * 16);
            } else {
                int j = i - 384; int r = j >> 3, ch = j & 7;
                CPA16(vsb + r * 144 + ch * 16,
                      (const char*)d_VtT + ((size_t)r * QPAD + k0) * 2 + ch * 16);
            }
        }
    }
    CPA_COMMIT();

    for (int t = t0; t < tend; t++) {
        int cur = (t - t0) & 1;
        if (t + 1 < tend) {
            int nb = cur ^ 1;
            int k0 = (t + 1) * KT;
            for (int i = tid; i < 704; i += 256) {
                if (i < 384) {
                    int r = i / 6, ch = i % 6;
                    CPA16(ksb + nb * 7168 + r * 112 + ch * 16,
                          (const char*)d_Qk32 + (size_t)(k0 + r) * 96 + ch * 16);
                } else {
                    int j = i - 384; int r = j >> 3, ch = j & 7;
                    CPA16(vsb + nb * 5760 + r * 144 + ch * 16,
                          (const char*)d_VtT + ((size_t)r * QPAD + k0) * 2 + ch * 16);
                }
            }
        }
        CPA_COMMIT();
        CPA_WAIT1();
        __syncthreads();

        const uint32_t* K_ = Ks[cur];
        const uint32_t* V_ = Vs[cur];
#pragma unroll
        for (int h = 0; h < 2; h++) {
            float e[8][4];
#pragma unroll
            for (int nt = 0; nt < 8; nt++) {
                float S0 = 0.f, S1 = 0.f, S2 = 0.f, S3 = 0.f;
#pragma unroll
                for (int kc = 0; kc < 3; kc++) {
                    uint32_t b0 = K_[(nt * 8 + gid) * 28 + 8 * kc + tig];
                    uint32_t b1 = K_[(nt * 8 + gid) * 28 + 8 * kc + tig + 4];
                    MMA_BF16(S0, S1, S2, S3,
                             A[h][kc][0], A[h][kc][1], A[h][kc][2], A[h][kc][3], b0, b1);
                }
                e[nt][0] = ex2f(S0);
                e[nt][1] = ex2f(S1);
                e[nt][2] = ex2f(S2);
                e[nt][3] = ex2f(S3);
            }
#pragma unroll
            for (int kc = 0; kc < 4; kc++) {
                uint32_t a0 = packbf(e[2 * kc][1],     e[2 * kc][0]);
                uint32_t a1 = packbf(e[2 * kc][3],     e[2 * kc][2]);
                uint32_t a2 = packbf(e[2 * kc + 1][1], e[2 * kc + 1][0]);
                uint32_t a3 = packbf(e[2 * kc + 1][3], e[2 * kc + 1][2]);
#pragma unroll
                for (int nt = 0; nt < 5; nt++) {
                    uint32_t b0 = V_[(nt * 8 + gid) * 36 + 8 * kc + tig];
                    uint32_t b1 = V_[(nt * 8 + gid) * 36 + 8 * kc + tig + 4];
                    MMA_BF16(O[h][nt][0], O[h][nt][1], O[h][nt][2], O[h][nt][3],
                             a0, a1, a2, a3, b0, b1);
                }
            }
        }
        __syncthreads();
    }

    float* Op = d_Opart[split];
#pragma unroll
    for (int h = 0; h < 2; h++) {
        int q0r = qbase + h * 16 + gid, q1r = q0r + 8;
#pragma unroll
        for (int nt = 0; nt < 5; nt++) {
            *(float2*)&Op[q0r * 40 + nt * 8 + 2 * tig] = make_float2(O[h][nt][0], O[h][nt][1]);
            *(float2*)&Op[q1r * 40 + nt * 8 + 2 * tig] = make_float2(O[h][nt][2], O[h][nt][3]);
        }
    }
}

// ---------------- merge: h = relu(O/l + V); elem 35 = 1.0 (degree carrier) ----------------
__global__ void merge_kernel() {
    int i = blockIdx.x * blockDim.x + threadIdx.x;
    if (i >= N_NODES * FP) return;
    int q = i / FP, f = i - q * FP;
    float r;
    if (f == 35) {
        r = 1.0f;
    } else {
        float O = d_Opart[0][q * 40 + f] + d_Opart[1][q * 40 + f] + d_Opart[2][q * 40 + f];
        float l = d_Opart[0][q * 40 + 35] + d_Opart[1][q * 40 + 35] + d_Opart[2][q * 40 + 35];
        float v = d_Vex[q * 40 + f];
        r = fmaxf(fmaf(O, 1.0f / l, v), 0.f);
    }
    ((float*)d_h4)[i] = r;
}

// ---------------- SAGE scatter: thread-per-edge, v4 reductions (deg rides elem 35) ----------------
__global__ void scatter_kernel(const int* __restrict__ ei) {
    int e = blockIdx.x * blockDim.x + threadIdx.x;
    if (e >= E_EDGES) return;
    int is64 = d_is64;
    int src = is64 ? ei[2 * e] : ei[e];
    int dst = is64 ? ei[2 * (E_EDGES + e)] : ei[E_EDGES + e];
    const float4* hs = d_h4 + src * 9;
    float4* ag = d_agg4 + dst * 9;
#pragma unroll
    for (int i = 0; i < 9; i++) red4(ag + i, hs[i]);
}

// ---------------- SAGE combine + fused global max pool ----------------
__global__ __launch_bounds__(128) void sage_kernel(const float* __restrict__ Wll,
                                                   const float* __restrict__ bll,
                                                   const float* __restrict__ Wlr,
                                                   const int* __restrict__ bat) {
    __shared__ float Wl_s[F * F], Wr_s[F * F], bl_s[F];
    __shared__ float hs[F][33], as[F][33];
    __shared__ float rd[32];
    __shared__ int bs[32];
    int tid = threadIdx.x;
    int n0 = blockIdx.x * 32;
    int is64 = d_is64;
    const float* hf = (const float*)d_h4;
    const float* af = (const float*)d_agg4;
    for (int w = tid; w < F * F; w += 128) {
        Wl_s[w] = Wll[w];
        Wr_s[w] = Wlr[w];
    }
    if (tid < F) bl_s[tid] = bll[tid];
    if (tid < 32) {
        rd[tid] = 1.0f / fmaxf(af[(n0 + tid) * FP + 35], 1.0f);
        int node = n0 + tid;
        bs[tid] = is64 ? bat[2 * node] : bat[node];
    }
    for (int w = tid; w < 32 * F; w += 128) {
        int n = w / F, j = w % F;
        hs[j][n] = hf[(n0 + n) * FP + j];
        as[j][n] = af[(n0 + n) * FP + j];
    }
    __syncthreads();
    for (int w = tid; w < 32 * F; w += 128) {
        int n = w & 31, o = w >> 5;
        float a1 = 0.f, a2 = 0.f;
#pragma unroll
        for (int j = 0; j < F; j++) {
            a1 = fmaf(as[j][n], Wl_s[o * F + j], a1);
            a2 = fmaf(hs[j][n], Wr_s[o * F + j], a2);
        }
        float r = fmaf(a1, rd[n], bl_s[o]) + a2;
        r = fmaxf(r, 0.f);
        atomicMax((int*)&d_g[bs[n] * FP + o], __float_as_int(r));
    }
}

// ---------------- MLP head ----------------
__global__ __launch_bounds__(128) void mlp1_kernel(const float* __restrict__ Wg1,
                                                   const float* __restrict__ bg1) {
    __shared__ float gs[F][64];
    int tid = threadIdx.x;
    for (int w = tid; w < 64 * F; w += 128) {
        int b = w / F, d = w % F;
        gs[d][b] = d_g[b * FP + d];
    }
    __syncthreads();
    int j = blockIdx.x * 2 + (tid >> 6);
    int b = tid & 63;
    float acc = 0.f;
#pragma unroll
    for (int d = 0; d < F; d++) acc = fmaf(gs[d][b], __ldg(&Wg1[j * F + d]), acc);
    d_g1[b * H1 + j] = fmaxf(acc + bg1[j], 0.f);
}

__global__ void mlp2_kernel(const float* __restrict__ Wg2, const float* __restrict__ bg2) {
    int wid = (blockIdx.x * blockDim.x + threadIdx.x) >> 5;
    int lane = threadIdx.x & 31;
    if (wid >= B_GRAPHS * H2) return;
    int b = wid >> 7, j = wid & 127;
    float acc = 0.f;
    for (int d = lane; d < H1; d += 32)
        acc = fmaf(d_g1[b * H1 + d], Wg2[j * H1 + d], acc);
#pragma unroll
    for (int off = 16; off; off >>= 1) acc += __shfl_xor_sync(0xffffffffu, acc, off);
    if (lane == 0) d_g2[b * H2 + j] = acc + bg2[j];
}

__global__ void out_kernel(const float* __restrict__ Wo, const float* __restrict__ bo,
                           float* __restrict__ out) {
    int b = threadIdx.x;
    if (b < B_GRAPHS) {
        float acc = 0.f;
#pragma unroll
        for (int d = 0; d < H2; d++) acc = fmaf(d_g2[b * H2 + d], Wo[d], acc);
        out[b] = acc + bo[0];
    }
}

extern "C" void kernel_launch(void* const* d_in, const int* in_sizes, int n_in,
                              void* d_out, int out_size) {
    const float* x   = (const float*)d_in[0];
    const int*   ei  = (const int*)d_in[1];
    const int*   bat = (const int*)d_in[2];
    const float* Wq  = (const float*)d_in[3];
    const float* bq  = (const float*)d_in[4];
    const float* Wk  = (const float*)d_in[5];
    const float* bk  = (const float*)d_in[6];
    const float* Wv  = (const float*)d_in[7];
    const float* bv  = (const float*)d_in[8];
    const float* W3  = (const float*)d_in[9];
    const float* b3  = (const float*)d_in[10];
    const float* W5  = (const float*)d_in[11];
    const float* b5  = (const float*)d_in[12];
    const float* Wl  = (const float*)d_in[13];
    const float* bl  = (const float*)d_in[14];
    const float* Wll = (const float*)d_in[15];
    const float* bll = (const float*)d_in[16];
    const float* Wlr = (const float*)d_in[17];
    const float* Wg1 = (const float*)d_in[18];
    const float* bg1 = (const float*)d_in[19];
    const float* Wg2 = (const float*)d_in[20];
    const float* bg2 = (const float*)d_in[21];
    const float* Wo  = (const float*)d_in[22];
    const float* bo  = (const float*)d_in[23];
    float* out = (float*)d_out;

    setup_kernel<<<64, 256>>>(ei, Wl, W3, W5, b3, b5, bl, Wk, bk);
    proj_kernel<<<QPAD / 32, 256>>>(x, Wq, bq, Wv, bv);
    attn_kernel<<<dim3(47, NSPLIT), 256>>>();
    merge_kernel<<<(N_NODES * FP + 255) / 256, 256>>>();
    scatter_kernel<<<(E_EDGES + 255) / 256, 256>>>(ei);
    sage_kernel<<<N_NODES / 32, 128>>>(Wll, bll, Wlr, bat);
    mlp1_kernel<<<H1 / 2, 128>>>(Wg1, bg1);
    mlp2_kernel<<<B_GRAPHS * H2 / 4, 128>>>(Wg2, bg2);
    out_kernel<<<1, 64>>>(Wo, bo, out);
}

// round 10
// speedup vs baseline: 6.2865x; 1.0529x over previous
#include <cuda_runtime.h>
#include <cuda_bf16.h>
#include <math.h>
#include <stdint.h>

#define N_NODES 12000
#define F 35
#define FP 36
#define QPAD 12032
#define NSPLIT 3
#define KT 64
#define NTILES 188          // 188 * 64 = 12032 padded keys
#define E_EDGES 192000
#define B_GRAPHS 64
#define H1 1500
#define H2 128

// ---------------- scratch ----------------
__device__ __align__(16) uint32_t d_Kn32[QPAD * 24];  // queries bf16 [row][48]
__device__ __align__(16) uint32_t d_Qk32[QPAD * 24];  // keys bf16
__device__ __align__(16) uint16_t d_VtT[40 * QPAD];   // V^T bf16; row35=ones, pad cols=0
__device__ float d_Vex[QPAD * 40];
__device__ float d_Opart[NSPLIT][QPAD * 40];
__device__ float4 d_h4[N_NODES * 9];    // h, 36-stride; elem35 = 1.0 (deg carrier)
__device__ float4 d_agg4[N_NODES * 9];  // agg; elem35 accumulates degree
__device__ float d_Weff[F * F];
__device__ float d_beff[F];
__device__ float d_Wc[F * F];
__device__ float d_bc[F];
__device__ float d_g[B_GRAPHS * FP];
__device__ float d_g1[B_GRAPHS * H1];
__device__ float d_g2[B_GRAPHS * H2];
__device__ int d_is64;

__device__ __forceinline__ float ex2f(float x) {
    float r;
    asm("ex2.approx.f32 %0, %1;" : "=f"(r) : "f"(x));
    return r;
}
__device__ __forceinline__ uint32_t packbf(float hi, float lo) {
    uint32_t r;
    asm("cvt.rn.bf16x2.f32 %0, %1, %2;" : "=r"(r) : "f"(hi), "f"(lo));
    return r;
}
#define MMA_BF16(d0, d1, d2, d3, a0, a1, a2, a3, b0, b1)                                   \
    asm volatile(                                                                          \
        "mma.sync.aligned.m16n8k16.row.col.f32.bf16.bf16.f32 "                             \
        "{%0,%1,%2,%3},{%4,%5,%6,%7},{%8,%9},{%0,%1,%2,%3};"                               \
        : "+f"(d0), "+f"(d1), "+f"(d2), "+f"(d3)                                           \
        : "r"(a0), "r"(a1), "r"(a2), "r"(a3), "r"(b0), "r"(b1))
#define CPA16(dst, src) \
    asm volatile("cp.async.cg.shared.global [%0], [%1], 16;" :: "r"(dst), "l"(src))
#define CPA_COMMIT() asm volatile("cp.async.commit_group;")
#define CPA_WAIT1()  asm volatile("cp.async.wait_group 1;")

__device__ __forceinline__ void red4(float4* p, float4 v) {
    asm volatile("red.global.add.v4.f32 [%0], {%1,%2,%3,%4};"
                 :: "l"(p), "f"(v.x), "f"(v.y), "f"(v.z), "f"(v.w) : "memory");
}

// ---------------- setup: detect + pre1 + pre2 (block 0), zero (blocks 1+) ----------------
__global__ void setup_kernel(const int* __restrict__ ei,
                             const float* __restrict__ Wl, const float* __restrict__ W3,
                             const float* __restrict__ W5, const float* __restrict__ b3,
                             const float* __restrict__ b5, const float* __restrict__ bl,
                             const float* __restrict__ Wk, const float* __restrict__ bk) {
    int tid = threadIdx.x;
    if (blockIdx.x == 0) {
        if (tid == 0) {
            int all0 = 1;
            for (int i = 0; i < 16; i++)
                if (ei[2 * i + 1] != 0) all0 = 0;
            d_is64 = all0;
        }
        for (int idx = tid; idx < F * 36; idx += 256) {
            int o = idx / 36, k = idx % 36;
            if (k < F) {
                float w = Wl[o * 105 + 70 + k];
                for (int m = 0; m < F; m++) {
                    w = fmaf(Wl[o * 105 + m],      W3[(m * F + k) * 3 + 1], w);
                    w = fmaf(Wl[o * 105 + 35 + m], W5[(m * F + k) * 5 + 2], w);
                }
                d_Weff[o * F + k] = w;
            } else {
                float be = bl[o];
                for (int m = 0; m < F; m++) {
                    be = fmaf(Wl[o * 105 + m],      b3[m], be);
                    be = fmaf(Wl[o * 105 + 35 + m], b5[m], be);
                }
                d_beff[o] = be;
            }
        }
        __syncthreads();
        const float CS = 1.4426950408889634f / sqrtf((float)F);
        for (int idx = tid; idx < F * 36; idx += 256) {
            int o = idx / 36, j = idx % 36;
            if (j < F) {
                float w = 0.f;
                for (int k = 0; k < F; k++) w = fmaf(d_Weff[o * F + k], Wk[k * F + j], w);
                d_Wc[o * F + j] = w * CS;
            } else {
                float b = d_beff[o];
                for (int k = 0; k < F; k++) b = fmaf(d_Weff[o * F + k], bk[k], b);
                d_bc[o] = b * CS;
            }
        }
    } else {
        int i = (blockIdx.x - 1) * 256 + tid;
        int stride = (gridDim.x - 1) * 256;
        float* af = (float*)d_agg4;
        for (int k = i; k < N_NODES * FP; k += stride) af[k] = 0.f;
        for (int k = i; k < B_GRAPHS * FP; k += stride) d_g[k] = 0.f;
    }
}

// ---------------- proj: 32 nodes/block, 8 threads/node x 14 outputs ----------------
__global__ __launch_bounds__(256) void proj_kernel(const float* __restrict__ x,
                                                   const float* __restrict__ Wq,
                                                   const float* __restrict__ bq,
                                                   const float* __restrict__ Wv,
                                                   const float* __restrict__ bv) {
    __shared__ __align__(16) float Wall[112 * 36];
    __shared__ float bsh[112];
    __shared__ __align__(16) float4 xs4[9][32];
    __shared__ float outS[32 * 113];
    int tid = threadIdx.x;
    int node0 = blockIdx.x * 32;

    for (int idx = tid; idx < 112 * 36; idx += 256) {
        int o = idx / 36, j = idx % 36;
        float v = 0.f;
        if (j < F && o < 105) {
            if (o < 35)      v = Wq[o * 35 + j];
            else if (o < 70) v = Wv[(o - 35) * 35 + j];
            else             v = d_Wc[(o - 70) * 35 + j];
        }
        Wall[idx] = v;
    }
    if (tid < 112) {
        float b = 0.f;
        if (tid < 35)       b = bq[tid];
        else if (tid < 70)  b = bv[tid - 35];
        else if (tid < 105) b = d_bc[tid - 70];
        bsh[tid] = b;
    }
    {
        float* xsf = (float*)xs4;
        for (int idx = tid; idx < 32 * 35; idx += 256) {
            int n = idx / 35, j = idx % 35;
            float v = (node0 + n < N_NODES) ? x[node0 * 35 + idx] : 0.f;
            xsf[(j >> 2) * 128 + n * 4 + (j & 3)] = v;
        }
        if (tid < 32) xsf[8 * 128 + tid * 4 + 3] = 0.f;
    }
    __syncthreads();

    int c = tid >> 5;
    int n = tid & 31;
    float4 xv[9];
#pragma unroll
    for (int j4 = 0; j4 < 9; j4++) xv[j4] = xs4[j4][n];
    int o0 = c * 14;
    float acc[14];
#pragma unroll
    for (int k = 0; k < 14; k++) acc[k] = bsh[o0 + k];
#pragma unroll
    for (int j4 = 0; j4 < 9; j4++) {
        float4 xq = xv[j4];
#pragma unroll
        for (int k = 0; k < 14; k++) {
            const float4 wv = *(const float4*)&Wall[(o0 + k) * 36 + j4 * 4];
            acc[k] = fmaf(wv.x, xq.x, acc[k]);
            acc[k] = fmaf(wv.y, xq.y, acc[k]);
            acc[k] = fmaf(wv.z, xq.z, acc[k]);
            acc[k] = fmaf(wv.w, xq.w, acc[k]);
        }
    }
#pragma unroll
    for (int k = 0; k < 14; k++) outS[n * 113 + o0 + k] = acc[k];
    __syncthreads();

    // Kn bf16 (queries); pad nodes -> 0
    for (int idx = tid; idx < 32 * 24; idx += 256) {
        int nn = idx / 24, wd = idx % 24;
        int real = (node0 + nn < N_NODES);
        int f0 = 2 * wd;
        float v0 = (real && f0 < 35)     ? outS[nn * 113 + 70 + f0]     : 0.f;
        float v1 = (real && f0 + 1 < 35) ? outS[nn * 113 + 70 + f0 + 1] : 0.f;
        d_Kn32[(node0 + nn) * 24 + wd] = packbf(v1, v0);
    }
    // Qk bf16 (keys); pad -> 0
    for (int idx = tid; idx < 32 * 24; idx += 256) {
        int nn = idx / 24, wd = idx % 24;
        int real = (node0 + nn < N_NODES);
        int f0 = 2 * wd;
        float v0 = (real && f0 < 35)     ? outS[nn * 113 + f0]     : 0.f;
        float v1 = (real && f0 + 1 < 35) ? outS[nn * 113 + f0 + 1] : 0.f;
        d_Qk32[(node0 + nn) * 24 + wd] = packbf(v1, v0);
    }
    // V^T bf16; row 35 = ones for real nodes, 0 for pad (kills pad-key contributions)
    for (int idx = tid; idx < 36 * 32; idx += 256) {
        int f = idx >> 5, nn = idx & 31;
        int real = (node0 + nn < N_NODES);
        float v = real ? ((f < 35) ? outS[nn * 113 + 35 + f] : 1.0f) : 0.f;
        d_VtT[f * QPAD + node0 + nn] = __bfloat16_as_ushort(__float2bfloat16(v));
    }
    // Vex exact f32
    for (int idx = tid; idx < 32 * 40; idx += 256) {
        int nn = idx / 40, f = idx % 40;
        int real = (node0 + nn < N_NODES);
        d_Vex[(node0 + nn) * 40 + f] = (real && f < 35) ? outS[nn * 113 + 35 + f] : 0.f;
    }
}

// ---------------- bf16 flash attention: 256 q/CTA, 32 q/warp, 64-key tiles ----------------
// Inner loop reordered: each K/V fragment load feeds BOTH 16-query halves.
__global__ __launch_bounds__(256) void attn_kernel() {
    __shared__ __align__(16) uint32_t Ks[2][KT * 28];  // keys [64][56] bf16
    __shared__ __align__(16) uint32_t Vs[2][40 * 36];  // V^T [40][72] bf16

    int tid = threadIdx.x;
    int w = tid >> 5, lane = tid & 31;
    int gid = lane >> 2, tig = lane & 3;
    int qbase = blockIdx.x * 256 + w * 32;
    int split = blockIdx.y;
    int t0 = split * 63;
    int tend = (split == 2) ? NTILES : t0 + 63;

    uint32_t A[2][3][4];
#pragma unroll
    for (int h = 0; h < 2; h++)
#pragma unroll
        for (int kc = 0; kc < 3; kc++) {
            int r0 = qbase + h * 16 + gid;
            A[h][kc][0] = d_Kn32[r0 * 24 + 8 * kc + tig];
            A[h][kc][1] = d_Kn32[(r0 + 8) * 24 + 8 * kc + tig];
            A[h][kc][2] = d_Kn32[r0 * 24 + 8 * kc + tig + 4];
            A[h][kc][3] = d_Kn32[(r0 + 8) * 24 + 8 * kc + tig + 4];
        }
    float O[2][5][4];
#pragma unroll
    for (int h = 0; h < 2; h++)
#pragma unroll
        for (int nt = 0; nt < 5; nt++)
#pragma unroll
            for (int r = 0; r < 4; r++) O[h][nt][r] = 0.f;

    uint32_t ksb = (uint32_t)__cvta_generic_to_shared(&Ks[0][0]);
    uint32_t vsb = (uint32_t)__cvta_generic_to_shared(&Vs[0][0]);

    {
        int k0 = t0 * KT;
        for (int i = tid; i < 704; i += 256) {
            if (i < 384) {
                int r = i / 6, ch = i % 6;
                CPA16(ksb + r * 112 + ch * 16,
                      (const char*)d_Qk32 + (size_t)(k0 + r) * 96 + ch * 16);
            } else {
                int j = i - 384; int r = j >> 3, ch = j & 7;
                CPA16(vsb + r * 144 + ch * 16,
                      (const char*)d_VtT + ((size_t)r * QPAD + k0) * 2 + ch * 16);
            }
        }
    }
    CPA_COMMIT();

    for (int t = t0; t < tend; t++) {
        int cur = (t - t0) & 1;
        if (t + 1 < tend) {
            int nb = cur ^ 1;
            int k0 = (t + 1) * KT;
            for (int i = tid; i < 704; i += 256) {
                if (i < 384) {
                    int r = i / 6, ch = i % 6;
                    CPA16(ksb + nb * 7168 + r * 112 + ch * 16,
                          (const char*)d_Qk32 + (size_t)(k0 + r) * 96 + ch * 16);
                } else {
                    int j = i - 384; int r = j >> 3, ch = j & 7;
                    CPA16(vsb + nb * 5760 + r * 144 + ch * 16,
                          (const char*)d_VtT + ((size_t)r * QPAD + k0) * 2 + ch * 16);
                }
            }
        }
        CPA_COMMIT();
        CPA_WAIT1();
        __syncthreads();

        const uint32_t* K_ = Ks[cur];
        const uint32_t* V_ = Vs[cur];

        // two nt-chunks of 4 (keys 32c..32c+31); shared fragments feed both halves
#pragma unroll
        for (int c = 0; c < 2; c++) {
            float S[2][4][4];
#pragma unroll
            for (int h = 0; h < 2; h++)
#pragma unroll
                for (int n4 = 0; n4 < 4; n4++)
#pragma unroll
                    for (int r = 0; r < 4; r++) S[h][n4][r] = 0.f;
            // ---- S chunk: Kn(2x16x48) @ keys^T ----
#pragma unroll
            for (int kc = 0; kc < 3; kc++) {
#pragma unroll
                for (int n4 = 0; n4 < 4; n4++) {
                    int nt = 4 * c + n4;
                    uint32_t b0 = K_[(nt * 8 + gid) * 28 + 8 * kc + tig];
                    uint32_t b1 = K_[(nt * 8 + gid) * 28 + 8 * kc + tig + 4];
                    MMA_BF16(S[0][n4][0], S[0][n4][1], S[0][n4][2], S[0][n4][3],
                             A[0][kc][0], A[0][kc][1], A[0][kc][2], A[0][kc][3], b0, b1);
                    MMA_BF16(S[1][n4][0], S[1][n4][1], S[1][n4][2], S[1][n4][3],
                             A[1][kc][0], A[1][kc][1], A[1][kc][2], A[1][kc][3], b0, b1);
                }
            }
            // ---- exp2 + pack P fragments ----
            uint32_t aP[2][2][4];
#pragma unroll
            for (int h = 0; h < 2; h++)
#pragma unroll
                for (int n4 = 0; n4 < 4; n4++)
#pragma unroll
                    for (int r = 0; r < 4; r++) S[h][n4][r] = ex2f(S[h][n4][r]);
#pragma unroll
            for (int h = 0; h < 2; h++)
#pragma unroll
                for (int ks = 0; ks < 2; ks++) {
                    aP[h][ks][0] = packbf(S[h][2 * ks][1],     S[h][2 * ks][0]);
                    aP[h][ks][1] = packbf(S[h][2 * ks][3],     S[h][2 * ks][2]);
                    aP[h][ks][2] = packbf(S[h][2 * ks + 1][1], S[h][2 * ks + 1][0]);
                    aP[h][ks][3] = packbf(S[h][2 * ks + 1][3], S[h][2 * ks + 1][2]);
                }
            // ---- O += P chunk @ V ----
#pragma unroll
            for (int ks = 0; ks < 2; ks++) {
                int kc = 2 * c + ks;
#pragma unroll
                for (int nt = 0; nt < 5; nt++) {
                    uint32_t b0 = V_[(nt * 8 + gid) * 36 + 8 * kc + tig];
                    uint32_t b1 = V_[(nt * 8 + gid) * 36 + 8 * kc + tig + 4];
                    MMA_BF16(O[0][nt][0], O[0][nt][1], O[0][nt][2], O[0][nt][3],
                             aP[0][ks][0], aP[0][ks][1], aP[0][ks][2], aP[0][ks][3], b0, b1);
                    MMA_BF16(O[1][nt][0], O[1][nt][1], O[1][nt][2], O[1][nt][3],
                             aP[1][ks][0], aP[1][ks][1], aP[1][ks][2], aP[1][ks][3], b0, b1);
                }
            }
        }
        __syncthreads();
    }

    float* Op = d_Opart[split];
#pragma unroll
    for (int h = 0; h < 2; h++) {
        int q0r = qbase + h * 16 + gid, q1r = q0r + 8;
#pragma unroll
        for (int nt = 0; nt < 5; nt++) {
            *(float2*)&Op[q0r * 40 + nt * 8 + 2 * tig] = make_float2(O[h][nt][0], O[h][nt][1]);
            *(float2*)&Op[q1r * 40 + nt * 8 + 2 * tig] = make_float2(O[h][nt][2], O[h][nt][3]);
        }
    }
}

// ---------------- merge: h = relu(O/l + V); elem 35 = 1.0 (degree carrier) ----------------
__global__ void merge_kernel() {
    int i = blockIdx.x * blockDim.x + threadIdx.x;
    if (i >= N_NODES * FP) return;
    int q = i / FP, f = i - q * FP;
    float r;
    if (f == 35) {
        r = 1.0f;
    } else {
        float O = d_Opart[0][q * 40 + f] + d_Opart[1][q * 40 + f] + d_Opart[2][q * 40 + f];
        float l = d_Opart[0][q * 40 + 35] + d_Opart[1][q * 40 + 35] + d_Opart[2][q * 40 + 35];
        float v = d_Vex[q * 40 + f];
        r = fmaxf(fmaf(O, 1.0f / l, v), 0.f);
    }
    ((float*)d_h4)[i] = r;
}

// ---------------- SAGE scatter: thread-per-edge, v4 reductions (deg rides elem 35) ----------------
__global__ void scatter_kernel(const int* __restrict__ ei) {
    int e = blockIdx.x * blockDim.x + threadIdx.x;
    if (e >= E_EDGES) return;
    int is64 = d_is64;
    int src = is64 ? ei[2 * e] : ei[e];
    int dst = is64 ? ei[2 * (E_EDGES + e)] : ei[E_EDGES + e];
    const float4* hs = d_h4 + src * 9;
    float4* ag = d_agg4 + dst * 9;
#pragma unroll
    for (int i = 0; i < 9; i++) red4(ag + i, hs[i]);
}

// ---------------- SAGE combine + fused global max pool ----------------
__global__ __launch_bounds__(128) void sage_kernel(const float* __restrict__ Wll,
                                                   const float* __restrict__ bll,
                                                   const float* __restrict__ Wlr,
                                                   const int* __restrict__ bat) {
    __shared__ float Wl_s[F * F], Wr_s[F * F], bl_s[F];
    __shared__ float hs[F][33], as[F][33];
    __shared__ float rd[32];
    __shared__ int bs[32];
    int tid = threadIdx.x;
    int n0 = blockIdx.x * 32;
    int is64 = d_is64;
    const float* hf = (const float*)d_h4;
    const float* af = (const float*)d_agg4;
    for (int w = tid; w < F * F; w += 128) {
        Wl_s[w] = Wll[w];
        Wr_s[w] = Wlr[w];
    }
    if (tid < F) bl_s[tid] = bll[tid];
    if (tid < 32) {
        rd[tid] = 1.0f / fmaxf(af[(n0 + tid) * FP + 35], 1.0f);
        int node = n0 + tid;
        bs[tid] = is64 ? bat[2 * node] : bat[node];
    }
    for (int w = tid; w < 32 * F; w += 128) {
        int n = w / F, j = w % F;
        hs[j][n] = hf[(n0 + n) * FP + j];
        as[j][n] = af[(n0 + n) * FP + j];
    }
    __syncthreads();
    for (int w = tid; w < 32 * F; w += 128) {
        int n = w & 31, o = w >> 5;
        float a1 = 0.f, a2 = 0.f;
#pragma unroll
        for (int j = 0; j < F; j++) {
            a1 = fmaf(as[j][n], Wl_s[o * F + j], a1);
            a2 = fmaf(hs[j][n], Wr_s[o * F + j], a2);
        }
        float r = fmaf(a1, rd[n], bl_s[o]) + a2;
        r = fmaxf(r, 0.f);
        atomicMax((int*)&d_g[bs[n] * FP + o], __float_as_int(r));
    }
}

// ---------------- MLP head ----------------
__global__ __launch_bounds__(128) void mlp1_kernel(const float* __restrict__ Wg1,
                                                   const float* __restrict__ bg1) {
    __shared__ float gs[F][64];
    int tid = threadIdx.x;
    for (int w = tid; w < 64 * F; w += 128) {
        int b = w / F, d = w % F;
        gs[d][b] = d_g[b * FP + d];
    }
    __syncthreads();
    int j = blockIdx.x * 2 + (tid >> 6);
    int b = tid & 63;
    float acc = 0.f;
#pragma unroll
    for (int d = 0; d < F; d++) acc = fmaf(gs[d][b], __ldg(&Wg1[j * F + d]), acc);
    d_g1[b * H1 + j] = fmaxf(acc + bg1[j], 0.f);
}

__global__ void mlp2_kernel(const float* __restrict__ Wg2, const float* __restrict__ bg2) {
    int wid = (blockIdx.x * blockDim.x + threadIdx.x) >> 5;
    int lane = threadIdx.x & 31;
    if (wid >= B_GRAPHS * H2) return;
    int b = wid >> 7, j = wid & 127;
    float acc = 0.f;
    for (int d = lane; d < H1; d += 32)
        acc = fmaf(d_g1[b * H1 + d], Wg2[j * H1 + d], acc);
#pragma unroll
    for (int off = 16; off; off >>= 1) acc += __shfl_xor_sync(0xffffffffu, acc, off);
    if (lane == 0) d_g2[b * H2 + j] = acc + bg2[j];
}

__global__ void out_kernel(const float* __restrict__ Wo, const float* __restrict__ bo,
                           float* __restrict__ out) {
    int b = threadIdx.x;
    if (b < B_GRAPHS) {
        float acc = 0.f;
#pragma unroll
        for (int d = 0; d < H2; d++) acc = fmaf(d_g2[b * H2 + d], Wo[d], acc);
        out[b] = acc + bo[0];
    }
}

extern "C" void kernel_launch(void* const* d_in, const int* in_sizes, int n_in,
                              void* d_out, int out_size) {
    const float* x   = (const float*)d_in[0];
    const int*   ei  = (const int*)d_in[1];
    const int*   bat = (const int*)d_in[2];
    const float* Wq  = (const float*)d_in[3];
    const float* bq  = (const float*)d_in[4];
    const float* Wk  = (const float*)d_in[5];
    const float* bk  = (const float*)d_in[6];
    const float* Wv  = (const float*)d_in[7];
    const float* bv  = (const float*)d_in[8];
    const float* W3  = (const float*)d_in[9];
    const float* b3  = (const float*)d_in[10];
    const float* W5  = (const float*)d_in[11];
    const float* b5  = (const float*)d_in[12];
    const float* Wl  = (const float*)d_in[13];
    const float* bl  = (const float*)d_in[14];
    const float* Wll = (const float*)d_in[15];
    const float* bll = (const float*)d_in[16];
    const float* Wlr = (const float*)d_in[17];
    const float* Wg1 = (const float*)d_in[18];
    const float* bg1 = (const float*)d_in[19];
    const float* Wg2 = (const float*)d_in[20];
    const float* bg2 = (const float*)d_in[21];
    const float* Wo  = (const float*)d_in[22];
    const float* bo  = (const float*)d_in[23];
    float* out = (float*)d_out;

    setup_kernel<<<64, 256>>>(ei, Wl, W3, W5, b3, b5, bl, Wk, bk);
    proj_kernel<<<QPAD / 32, 256>>>(x, Wq, bq, Wv, bv);
    attn_kernel<<<dim3(47, NSPLIT), 256>>>();
    merge_kernel<<<(N_NODES * FP + 255) / 256, 256>>>();
    scatter_kernel<<<(E_EDGES + 255) / 256, 256>>>(ei);
    sage_kernel<<<N_NODES / 32, 128>>>(Wll, bll, Wlr, bat);
    mlp1_kernel<<<H1 / 2, 128>>>(Wg1, bg1);
    mlp2_kernel<<<B_GRAPHS * H2 / 4, 128>>>(Wg2, bg2);
    out_kernel<<<1, 64>>>(Wo, bo, out);
}

// round 11
// speedup vs baseline: 6.2876x; 1.0002x over previous
#include <cuda_runtime.h>
#include <cuda_bf16.h>
#include <math.h>
#include <stdint.h>

#define N_NODES 12000
#define F 35
#define FP 36
#define QPAD 12032
#define NSPLIT 3
#define KT 64
#define NTILES 188          // 188 * 64 = 12032 padded keys
#define E_EDGES 192000
#define B_GRAPHS 64
#define H1 1500
#define H2 128

// ---------------- scratch ----------------
__device__ __align__(16) uint32_t d_Kn32[QPAD * 24];  // queries bf16 [row][48]
__device__ __align__(16) uint32_t d_Qk32[QPAD * 24];  // keys bf16
__device__ __align__(16) uint16_t d_VtT[40 * QPAD];   // V^T bf16; row35=ones, pad cols=0
__device__ float d_Vex[QPAD * 40];
__device__ float d_Opart[NSPLIT][QPAD * 40];
__device__ float4 d_h4[N_NODES * 9];    // h, 36-stride; elem35 = 1.0 (deg carrier)
__device__ float4 d_agg4[N_NODES * 9];  // agg; elem35 accumulates degree
__device__ float d_Weff[F * F];
__device__ float d_beff[F];
__device__ float d_Wc[F * F];
__device__ float d_bc[F];
__device__ float d_g[B_GRAPHS * FP];
__device__ float d_g1[B_GRAPHS * H1];
__device__ float d_g2[B_GRAPHS * H2];
__device__ int d_is64;

__device__ __forceinline__ float ex2f(float x) {
    float r;
    asm("ex2.approx.f32 %0, %1;" : "=f"(r) : "f"(x));
    return r;
}
__device__ __forceinline__ uint32_t packbf(float hi, float lo) {
    uint32_t r;
    asm("cvt.rn.bf16x2.f32 %0, %1, %2;" : "=r"(r) : "f"(hi), "f"(lo));
    return r;
}
#define MMA_BF16(d0, d1, d2, d3, a0, a1, a2, a3, b0, b1)                                   \
    asm volatile(                                                                          \
        "mma.sync.aligned.m16n8k16.row.col.f32.bf16.bf16.f32 "                             \
        "{%0,%1,%2,%3},{%4,%5,%6,%7},{%8,%9},{%0,%1,%2,%3};"                               \
        : "+f"(d0), "+f"(d1), "+f"(d2), "+f"(d3)                                           \
        : "r"(a0), "r"(a1), "r"(a2), "r"(a3), "r"(b0), "r"(b1))
#define CPA16(dst, src) \
    asm volatile("cp.async.cg.shared.global [%0], [%1], 16;" :: "r"(dst), "l"(src))
#define CPA_COMMIT() asm volatile("cp.async.commit_group;")
#define CPA_WAIT1()  asm volatile("cp.async.wait_group 1;")

__device__ __forceinline__ void red4(float4* p, float4 v) {
    asm volatile("red.global.add.v4.f32 [%0], {%1,%2,%3,%4};"
                 :: "l"(p), "f"(v.x), "f"(v.y), "f"(v.z), "f"(v.w) : "memory");
}

// ---------------- setup: detect + pre1 + pre2 (block 0), zero (blocks 1+) ----------------
__global__ void setup_kernel(const int* __restrict__ ei,
                             const float* __restrict__ Wl, const float* __restrict__ W3,
                             const float* __restrict__ W5, const float* __restrict__ b3,
                             const float* __restrict__ b5, const float* __restrict__ bl,
                             const float* __restrict__ Wk, const float* __restrict__ bk) {
    int tid = threadIdx.x;
    if (blockIdx.x == 0) {
        if (tid == 0) {
            int all0 = 1;
            for (int i = 0; i < 16; i++)
                if (ei[2 * i + 1] != 0) all0 = 0;
            d_is64 = all0;
        }
        for (int idx = tid; idx < F * 36; idx += 256) {
            int o = idx / 36, k = idx % 36;
            if (k < F) {
                float w = Wl[o * 105 + 70 + k];
                for (int m = 0; m < F; m++) {
                    w = fmaf(Wl[o * 105 + m],      W3[(m * F + k) * 3 + 1], w);
                    w = fmaf(Wl[o * 105 + 35 + m], W5[(m * F + k) * 5 + 2], w);
                }
                d_Weff[o * F + k] = w;
            } else {
                float be = bl[o];
                for (int m = 0; m < F; m++) {
                    be = fmaf(Wl[o * 105 + m],      b3[m], be);
                    be = fmaf(Wl[o * 105 + 35 + m], b5[m], be);
                }
                d_beff[o] = be;
            }
        }
        __syncthreads();
        const float CS = 1.4426950408889634f / sqrtf((float)F);
        for (int idx = tid; idx < F * 36; idx += 256) {
            int o = idx / 36, j = idx % 36;
            if (j < F) {
                float w = 0.f;
                for (int k = 0; k < F; k++) w = fmaf(d_Weff[o * F + k], Wk[k * F + j], w);
                d_Wc[o * F + j] = w * CS;
            } else {
                float b = d_beff[o];
                for (int k = 0; k < F; k++) b = fmaf(d_Weff[o * F + k], bk[k], b);
                d_bc[o] = b * CS;
            }
        }
    } else {
        int i = (blockIdx.x - 1) * 256 + tid;
        int stride = (gridDim.x - 1) * 256;
        float* af = (float*)d_agg4;
        for (int k = i; k < N_NODES * FP; k += stride) af[k] = 0.f;
        for (int k = i; k < B_GRAPHS * FP; k += stride) d_g[k] = 0.f;
    }
}

// ---------------- proj: 32 nodes/block, 8 threads/node x 14 outputs ----------------
__global__ __launch_bounds__(256) void proj_kernel(const float* __restrict__ x,
                                                   const float* __restrict__ Wq,
                                                   const float* __restrict__ bq,
                                                   const float* __restrict__ Wv,
                                                   const float* __restrict__ bv) {
    __shared__ __align__(16) float Wall[112 * 36];
    __shared__ float bsh[112];
    __shared__ __align__(16) float4 xs4[9][32];
    __shared__ float outS[32 * 113];
    int tid = threadIdx.x;
    int node0 = blockIdx.x * 32;

    for (int idx = tid; idx < 112 * 36; idx += 256) {
        int o = idx / 36, j = idx % 36;
        float v = 0.f;
        if (j < F && o < 105) {
            if (o < 35)      v = Wq[o * 35 + j];
            else if (o < 70) v = Wv[(o - 35) * 35 + j];
            else             v = d_Wc[(o - 70) * 35 + j];
        }
        Wall[idx] = v;
    }
    if (tid < 112) {
        float b = 0.f;
        if (tid < 35)       b = bq[tid];
        else if (tid < 70)  b = bv[tid - 35];
        else if (tid < 105) b = d_bc[tid - 70];
        bsh[tid] = b;
    }
    {
        float* xsf = (float*)xs4;
        for (int idx = tid; idx < 32 * 35; idx += 256) {
            int n = idx / 35, j = idx % 35;
            float v = (node0 + n < N_NODES) ? x[node0 * 35 + idx] : 0.f;
            xsf[(j >> 2) * 128 + n * 4 + (j & 3)] = v;
        }
        if (tid < 32) xsf[8 * 128 + tid * 4 + 3] = 0.f;
    }
    __syncthreads();

    int c = tid >> 5;
    int n = tid & 31;
    float4 xv[9];
#pragma unroll
    for (int j4 = 0; j4 < 9; j4++) xv[j4] = xs4[j4][n];
    int o0 = c * 14;
    float acc[14];
#pragma unroll
    for (int k = 0; k < 14; k++) acc[k] = bsh[o0 + k];
#pragma unroll
    for (int j4 = 0; j4 < 9; j4++) {
        float4 xq = xv[j4];
#pragma unroll
        for (int k = 0; k < 14; k++) {
            const float4 wv = *(const float4*)&Wall[(o0 + k) * 36 + j4 * 4];
            acc[k] = fmaf(wv.x, xq.x, acc[k]);
            acc[k] = fmaf(wv.y, xq.y, acc[k]);
            acc[k] = fmaf(wv.z, xq.z, acc[k]);
            acc[k] = fmaf(wv.w, xq.w, acc[k]);
        }
    }
#pragma unroll
    for (int k = 0; k < 14; k++) outS[n * 113 + o0 + k] = acc[k];
    __syncthreads();

    // Kn bf16 (queries); pad nodes -> 0
    for (int idx = tid; idx < 32 * 24; idx += 256) {
        int nn = idx / 24, wd = idx % 24;
        int real = (node0 + nn < N_NODES);
        int f0 = 2 * wd;
        float v0 = (real && f0 < 35)     ? outS[nn * 113 + 70 + f0]     : 0.f;
        float v1 = (real && f0 + 1 < 35) ? outS[nn * 113 + 70 + f0 + 1] : 0.f;
        d_Kn32[(node0 + nn) * 24 + wd] = packbf(v1, v0);
    }
    // Qk bf16 (keys); pad -> 0
    for (int idx = tid; idx < 32 * 24; idx += 256) {
        int nn = idx / 24, wd = idx % 24;
        int real = (node0 + nn < N_NODES);
        int f0 = 2 * wd;
        float v0 = (real && f0 < 35)     ? outS[nn * 113 + f0]     : 0.f;
        float v1 = (real && f0 + 1 < 35) ? outS[nn * 113 + f0 + 1] : 0.f;
        d_Qk32[(node0 + nn) * 24 + wd] = packbf(v1, v0);
    }
    // V^T bf16; row 35 = ones for real nodes, 0 for pad (kills pad-key contributions)
    for (int idx = tid; idx < 36 * 32; idx += 256) {
        int f = idx >> 5, nn = idx & 31;
        int real = (node0 + nn < N_NODES);
        float v = real ? ((f < 35) ? outS[nn * 113 + 35 + f] : 1.0f) : 0.f;
        d_VtT[f * QPAD + node0 + nn] = __bfloat16_as_ushort(__float2bfloat16(v));
    }
    // Vex exact f32
    for (int idx = tid; idx < 32 * 40; idx += 256) {
        int nn = idx / 40, f = idx % 40;
        int real = (node0 + nn < N_NODES);
        d_Vex[(node0 + nn) * 40 + f] = (real && f < 35) ? outS[nn * 113 + 35 + f] : 0.f;
    }
}

// ---------------- bf16 flash attention: 256 q/CTA, 32 q/warp, 64-key tiles ----------------
// Inner loop reordered: each K/V fragment load feeds BOTH 16-query halves.
__global__ __launch_bounds__(256) void attn_kernel() {
    __shared__ __align__(16) uint32_t Ks[2][KT * 28];  // keys [64][56] bf16
    __shared__ __align__(16) uint32_t Vs[2][40 * 36];  // V^T [40][72] bf16

    int tid = threadIdx.x;
    int w = tid >> 5, lane = tid & 31;
    int gid = lane >> 2, tig = lane & 3;
    int qbase = blockIdx.x * 256 + w * 32;
    int split = blockIdx.y;
    int t0 = split * 63;
    int tend = (split == 2) ? NTILES : t0 + 63;

    uint32_t A[2][3][4];
#pragma unroll
    for (int h = 0; h < 2; h++)
#pragma unroll
        for (int kc = 0; kc < 3; kc++) {
            int r0 = qbase + h * 16 + gid;
            A[h][kc][0] = d_Kn32[r0 * 24 + 8 * kc + tig];
            A[h][kc][1] = d_Kn32[(r0 + 8) * 24 + 8 * kc + tig];
            A[h][kc][2] = d_Kn32[r0 * 24 + 8 * kc + tig + 4];
            A[h][kc][3] = d_Kn32[(r0 + 8) * 24 + 8 * kc + tig + 4];
        }
    float O[2][5][4];
#pragma unroll
    for (int h = 0; h < 2; h++)
#pragma unroll
        for (int nt = 0; nt < 5; nt++)
#pragma unroll
            for (int r = 0; r < 4; r++) O[h][nt][r] = 0.f;

    uint32_t ksb = (uint32_t)__cvta_generic_to_shared(&Ks[0][0]);
    uint32_t vsb = (uint32_t)__cvta_generic_to_shared(&Vs[0][0]);

    {
        int k0 = t0 * KT;
        for (int i = tid; i < 704; i += 256) {
            if (i < 384) {
                int r = i / 6, ch = i % 6;
                CPA16(ksb + r * 112 + ch * 16,
                      (const char*)d_Qk32 + (size_t)(k0 + r) * 96 + ch * 16);
            } else {
                int j = i - 384; int r = j >> 3, ch = j & 7;
                CPA16(vsb + r * 144 + ch * 16,
                      (const char*)d_VtT + ((size_t)r * QPAD + k0) * 2 + ch * 16);
            }
        }
    }
    CPA_COMMIT();

    for (int t = t0; t < tend; t++) {
        int cur = (t - t0) & 1;
        if (t + 1 < tend) {
            int nb = cur ^ 1;
            int k0 = (t + 1) * KT;
            for (int i = tid; i < 704; i += 256) {
                if (i < 384) {
                    int r = i / 6, ch = i % 6;
                    CPA16(ksb + nb * 7168 + r * 112 + ch * 16,
                          (const char*)d_Qk32 + (size_t)(k0 + r) * 96 + ch * 16);
                } else {
                    int j = i - 384; int r = j >> 3, ch = j & 7;
                    CPA16(vsb + nb * 5760 + r * 144 + ch * 16,
                          (const char*)d_VtT + ((size_t)r * QPAD + k0) * 2 + ch * 16);
                }
            }
        }
        CPA_COMMIT();
        CPA_WAIT1();
        __syncthreads();

        const uint32_t* K_ = Ks[cur];
        const uint32_t* V_ = Vs[cur];

        // two nt-chunks of 4 (keys 32c..32c+31); shared fragments feed both halves
#pragma unroll
        for (int c = 0; c < 2; c++) {
            float S[2][4][4];
#pragma unroll
            for (int h = 0; h < 2; h++)
#pragma unroll
                for (int n4 = 0; n4 < 4; n4++)
#pragma unroll
                    for (int r = 0; r < 4; r++) S[h][n4][r] = 0.f;
            // ---- S chunk: Kn(2x16x48) @ keys^T ----
#pragma unroll
            for (int kc = 0; kc < 3; kc++) {
#pragma unroll
                for (int n4 = 0; n4 < 4; n4++) {
                    int nt = 4 * c + n4;
                    uint32_t b0 = K_[(nt * 8 + gid) * 28 + 8 * kc + tig];
                    uint32_t b1 = K_[(nt * 8 + gid) * 28 + 8 * kc + tig + 4];
                    MMA_BF16(S[0][n4][0], S[0][n4][1], S[0][n4][2], S[0][n4][3],
                             A[0][kc][0], A[0][kc][1], A[0][kc][2], A[0][kc][3], b0, b1);
                    MMA_BF16(S[1][n4][0], S[1][n4][1], S[1][n4][2], S[1][n4][3],
                             A[1][kc][0], A[1][kc][1], A[1][kc][2], A[1][kc][3], b0, b1);
                }
            }
            // ---- exp2 + pack P fragments ----
            uint32_t aP[2][2][4];
#pragma unroll
            for (int h = 0; h < 2; h++)
#pragma unroll
                for (int n4 = 0; n4 < 4; n4++)
#pragma unroll
                    for (int r = 0; r < 4; r++) S[h][n4][r] = ex2f(S[h][n4][r]);
#pragma unroll
            for (int h = 0; h < 2; h++)
#pragma unroll
                for (int ks = 0; ks < 2; ks++) {
                    aP[h][ks][0] = packbf(S[h][2 * ks][1],     S[h][2 * ks][0]);
                    aP[h][ks][1] = packbf(S[h][2 * ks][3],     S[h][2 * ks][2]);
                    aP[h][ks][2] = packbf(S[h][2 * ks + 1][1], S[h][2 * ks + 1][0]);
                    aP[h][ks][3] = packbf(S[h][2 * ks + 1][3], S[h][2 * ks + 1][2]);
                }
            // ---- O += P chunk @ V ----
#pragma unroll
            for (int ks = 0; ks < 2; ks++) {
                int kc = 2 * c + ks;
#pragma unroll
                for (int nt = 0; nt < 5; nt++) {
                    uint32_t b0 = V_[(nt * 8 + gid) * 36 + 8 * kc + tig];
                    uint32_t b1 = V_[(nt * 8 + gid) * 36 + 8 * kc + tig + 4];
                    MMA_BF16(O[0][nt][0], O[0][nt][1], O[0][nt][2], O[0][nt][3],
                             aP[0][ks][0], aP[0][ks][1], aP[0][ks][2], aP[0][ks][3], b0, b1);
                    MMA_BF16(O[1][nt][0], O[1][nt][1], O[1][nt][2], O[1][nt][3],
                             aP[1][ks][0], aP[1][ks][1], aP[1][ks][2], aP[1][ks][3], b0, b1);
                }
            }
        }
        __syncthreads();
    }

    float* Op = d_Opart[split];
#pragma unroll
    for (int h = 0; h < 2; h++) {
        int q0r = qbase + h * 16 + gid, q1r = q0r + 8;
#pragma unroll
        for (int nt = 0; nt < 5; nt++) {
            *(float2*)&Op[q0r * 40 + nt * 8 + 2 * tig] = make_float2(O[h][nt][0], O[h][nt][1]);
            *(float2*)&Op[q1r * 40 + nt * 8 + 2 * tig] = make_float2(O[h][nt][2], O[h][nt][3]);
        }
    }
}

// ---------------- merge: h = relu(O/l + V); elem 35 = 1.0 (degree carrier) ----------------
__global__ void merge_kernel() {
    int i = blockIdx.x * blockDim.x + threadIdx.x;
    if (i >= N_NODES * FP) return;
    int q = i / FP, f = i - q * FP;
    float r;
    if (f == 35) {
        r = 1.0f;
    } else {
        float O = d_Opart[0][q * 40 + f] + d_Opart[1][q * 40 + f] + d_Opart[2][q * 40 + f];
        float l = d_Opart[0][q * 40 + 35] + d_Opart[1][q * 40 + 35] + d_Opart[2][q * 40 + 35];
        float v = d_Vex[q * 40 + f];
        r = fmaxf(fmaf(O, 1.0f / l, v), 0.f);
    }
    ((float*)d_h4)[i] = r;
}

// ---------------- SAGE scatter: thread-per-edge, v4 reductions (deg rides elem 35) ----------------
__global__ void scatter_kernel(const int* __restrict__ ei) {
    int e = blockIdx.x * blockDim.x + threadIdx.x;
    if (e >= E_EDGES) return;
    int is64 = d_is64;
    int src = is64 ? ei[2 * e] : ei[e];
    int dst = is64 ? ei[2 * (E_EDGES + e)] : ei[E_EDGES + e];
    const float4* hs = d_h4 + src * 9;
    float4* ag = d_agg4 + dst * 9;
#pragma unroll
    for (int i = 0; i < 9; i++) red4(ag + i, hs[i]);
}

// ---------------- SAGE combine + fused global max pool ----------------
__global__ __launch_bounds__(128) void sage_kernel(const float* __restrict__ Wll,
                                                   const float* __restrict__ bll,
                                                   const float* __restrict__ Wlr,
                                                   const int* __restrict__ bat) {
    __shared__ float Wl_s[F * F], Wr_s[F * F], bl_s[F];
    __shared__ float hs[F][33], as[F][33];
    __shared__ float rd[32];
    __shared__ int bs[32];
    int tid = threadIdx.x;
    int n0 = blockIdx.x * 32;
    int is64 = d_is64;
    const float* hf = (const float*)d_h4;
    const float* af = (const float*)d_agg4;
    for (int w = tid; w < F * F; w += 128) {
        Wl_s[w] = Wll[w];
        Wr_s[w] = Wlr[w];
    }
    if (tid < F) bl_s[tid] = bll[tid];
    if (tid < 32) {
        rd[tid] = 1.0f / fmaxf(af[(n0 + tid) * FP + 35], 1.0f);
        int node = n0 + tid;
        bs[tid] = is64 ? bat[2 * node] : bat[node];
    }
    for (int w = tid; w < 32 * F; w += 128) {
        int n = w / F, j = w % F;
        hs[j][n] = hf[(n0 + n) * FP + j];
        as[j][n] = af[(n0 + n) * FP + j];
    }
    __syncthreads();
    for (int w = tid; w < 32 * F; w += 128) {
        int n = w & 31, o = w >> 5;
        float a1 = 0.f, a2 = 0.f;
#pragma unroll
        for (int j = 0; j < F; j++) {
            a1 = fmaf(as[j][n], Wl_s[o * F + j], a1);
            a2 = fmaf(hs[j][n], Wr_s[o * F + j], a2);
        }
        float r = fmaf(a1, rd[n], bl_s[o]) + a2;
        r = fmaxf(r, 0.f);
        atomicMax((int*)&d_g[bs[n] * FP + o], __float_as_int(r));
    }
}

// ---------------- MLP head ----------------
__global__ __launch_bounds__(128) void mlp1_kernel(const float* __restrict__ Wg1,
                                                   const float* __restrict__ bg1) {
    __shared__ float gs[F][64];
    int tid = threadIdx.x;
    for (int w = tid; w < 64 * F; w += 128) {
        int b = w / F, d = w % F;
        gs[d][b] = d_g[b * FP + d];
    }
    __syncthreads();
    int j = blockIdx.x * 2 + (tid >> 6);
    int b = tid & 63;
    float acc = 0.f;
#pragma unroll
    for (int d = 0; d < F; d++) acc = fmaf(gs[d][b], __ldg(&Wg1[j * F + d]), acc);
    d_g1[b * H1 + j] = fmaxf(acc + bg1[j], 0.f);
}

__global__ void mlp2_kernel(const float* __restrict__ Wg2, const float* __restrict__ bg2) {
    int wid = (blockIdx.x * blockDim.x + threadIdx.x) >> 5;
    int lane = threadIdx.x & 31;
    if (wid >= B_GRAPHS * H2) return;
    int b = wid >> 7, j = wid & 127;
    float acc = 0.f;
    for (int d = lane; d < H1; d += 32)
        acc = fmaf(d_g1[b * H1 + d], Wg2[j * H1 + d], acc);
#pragma unroll
    for (int off = 16; off; off >>= 1) acc += __shfl_xor_sync(0xffffffffu, acc, off);
    if (lane == 0) d_g2[b * H2 + j] = acc + bg2[j];
}

__global__ void out_kernel(const float* __restrict__ Wo, const float* __restrict__ bo,
                           float* __restrict__ out) {
    int b = threadIdx.x;
    if (b < B_GRAPHS) {
        float acc = 0.f;
#pragma unroll
        for (int d = 0; d < H2; d++) acc = fmaf(d_g2[b * H2 + d], Wo[d], acc);
        out[b] = acc + bo[0];
    }
}

extern "C" void kernel_launch(void* const* d_in, const int* in_sizes, int n_in,
                              void* d_out, int out_size) {
    const float* x   = (const float*)d_in[0];
    const int*   ei  = (const int*)d_in[1];
    const int*   bat = (const int*)d_in[2];
    const float* Wq  = (const float*)d_in[3];
    const float* bq  = (const float*)d_in[4];
    const float* Wk  = (const float*)d_in[5];
    const float* bk  = (const float*)d_in[6];
    const float* Wv  = (const float*)d_in[7];
    const float* bv  = (const float*)d_in[8];
    const float* W3  = (const float*)d_in[9];
    const float* b3  = (const float*)d_in[10];
    const float* W5  = (const float*)d_in[11];
    const float* b5  = (const float*)d_in[12];
    const float* Wl  = (const float*)d_in[13];
    const float* bl  = (const float*)d_in[14];
    const float* Wll = (const float*)d_in[15];
    const float* bll = (const float*)d_in[16];
    const float* Wlr = (const float*)d_in[17];
    const float* Wg1 = (const float*)d_in[18];
    const float* bg1 = (const float*)d_in[19];
    const float* Wg2 = (const float*)d_in[20];
    const float* bg2 = (const float*)d_in[21];
    const float* Wo  = (const float*)d_in[22];
    const float* bo  = (const float*)d_in[23];
    float* out = (float*)d_out;

    setup_kernel<<<64, 256>>>(ei, Wl, W3, W5, b3, b5, bl, Wk, bk);
    proj_kernel<<<QPAD / 32, 256>>>(x, Wq, bq, Wv, bv);
    attn_kernel<<<dim3(47, NSPLIT), 256>>>();
    merge_kernel<<<(N_NODES * FP + 255) / 256, 256>>>();
    scatter_kernel<<<(E_EDGES + 255) / 256, 256>>>(ei);
    sage_kernel<<<N_NODES / 32, 128>>>(Wll, bll, Wlr, bat);
    mlp1_kernel<<<H1 / 2, 128>>>(Wg1, bg1);
    mlp2_kernel<<<B_GRAPHS * H2 / 4, 128>>>(Wg2, bg2);
    out_kernel<<<1, 64>>>(Wo, bo, out);
}